// round 10
// baseline (speedup 1.0000x reference)
#include <cuda_runtime.h>
#include <cuda_bf16.h>
#include <cstdint>

// ---------------- problem constants ----------------
#define NF   133
#define EFE  14
#define HH   300
#define GG   200
#define TT   12
#define BB   4096
#define NPER 32
#define NNODE (BB*NPER)      // 131072
#define EEDGE (BB*64)        // 262144
#define RR1  550
#define RR2  378

// padded K per GEMM (storage, multiple of 64); P = storage K-panels of 64
#define KP_H0 192   // K=147, P=3,  NK16=10
#define KP_L  320   // K=300, P=5,  NK16=19
#define KP_HV 448   // K=433, P=7,  NK16=28
#define KP_R1 512   // K=500, P=8,  NK16=32
#define KP_R2 576   // K=550, P=9,  NK16=35
#define KP_R3 384   // K=378, P=6,  NK16=24

// N-tile width (per CTA) is fixed at 64.
#define NT_H  5     // ceil(300/64) -> 320
#define NT_R1 9     // 576
#define NT_R2 6     // 384
#define NT_R3 1     // 64

// ---------------- scratch ----------------
__device__ float g_h0[(size_t)EEDGE*HH];
__device__ float g_hA[(size_t)EEDGE*HH];
__device__ float g_hB[(size_t)EEDGE*HH];
__device__ float g_mv[(size_t)NNODE*HH];
__device__ float g_hv[(size_t)NNODE*HH];
__device__ float g_r1[(size_t)BB*RR1];
__device__ float g_r2[(size_t)BB*RR2];

__device__ __nv_bfloat16 g_Ae [(size_t)EEDGE*2*KP_L];
__device__ __nv_bfloat16 g_Ahv[(size_t)NNODE*2*KP_HV];
__device__ __nv_bfloat16 g_Ar1[(size_t)BB*2*KP_R1];
__device__ __nv_bfloat16 g_Ar2[(size_t)BB*2*KP_R2];
__device__ __nv_bfloat16 g_Ar3[(size_t)BB*2*KP_R3];

// W panels: [ntile][3P][64 rows x 128B] swizzled bf16
__device__ __nv_bfloat16 g_Wi [(size_t)NT_H *9 *64*64];
__device__ __nv_bfloat16 g_Wm [(size_t)NT_H *15*64*64];
__device__ __nv_bfloat16 g_Wa [(size_t)NT_H *21*64*64];
__device__ __nv_bfloat16 g_Wr1[(size_t)NT_R1*24*64*64];
__device__ __nv_bfloat16 g_Wr2[(size_t)NT_R2*27*64*64];
__device__ __nv_bfloat16 g_Wr3[(size_t)NT_R3*18*64*64];

// ---------------- helpers ----------------
__device__ __forceinline__ uint32_t smem_u32(const void* p){
    uint32_t a;
    asm("{ .reg .u64 t; cvta.to.shared.u64 t, %1; cvt.u32.u64 %0, t; }" : "=r"(a) : "l"(p));
    return a;
}
__device__ __forceinline__ void cp16(uint32_t dst, const void* src){
    asm volatile("cp.async.cg.shared.global [%0], [%1], 16;" :: "r"(dst), "l"(src));
}
__device__ __forceinline__ void cp_commit(){
    asm volatile("cp.async.commit_group;" ::: "memory");
}
__device__ __forceinline__ void ldm4(uint32_t& r0, uint32_t& r1, uint32_t& r2, uint32_t& r3, uint32_t addr){
    asm volatile("ldmatrix.sync.aligned.m8n8.x4.shared.b16 {%0,%1,%2,%3}, [%4];"
                 : "=r"(r0), "=r"(r1), "=r"(r2), "=r"(r3) : "r"(addr));
}
__device__ __forceinline__ void mma16816(float* c, const uint32_t* a, uint32_t b0, uint32_t b1){
    asm volatile("mma.sync.aligned.m16n8k16.row.col.f32.bf16.bf16.f32 "
                 "{%0,%1,%2,%3}, {%4,%5,%6,%7}, {%8,%9}, {%0,%1,%2,%3};"
                 : "+f"(c[0]), "+f"(c[1]), "+f"(c[2]), "+f"(c[3])
                 : "r"(a[0]), "r"(a[1]), "r"(a[2]), "r"(a[3]), "r"(b0), "r"(b1));
}
__device__ __forceinline__ void write_split(__nv_bfloat16* row, int Kpad, int k, float x){
    __nv_bfloat16 h = __float2bfloat16(x);
    row[k] = h;
    row[Kpad + k] = __float2bfloat16(x - __bfloat162float(h));
}
__device__ __forceinline__ uint32_t sw128(uint32_t off){ return off ^ ((off >> 3) & 0x70); }

// ---------------- weight prepack: fp32 W[K,N] -> swizzled bf16 panels ----------------
// panel order g in [0,3P): g<P -> hi[g], P<=g<2P -> lo[g-P], g>=2P -> hi[g-2P]
// (matches A panels: hi, hi, lo -> products Ah*Wh + Ah*Wl + Al*Wh)
__global__ void prepack_w(const float* __restrict__ W, __nv_bfloat16* __restrict__ out,
                          int K, int N, int P, int ntiles)
{
    int idx = blockIdx.x * 256 + threadIdx.x;
    const int per_panel = 64 * 64;
    int total = ntiles * 3 * P * per_panel;
    if (idx >= total) return;
    int t   = idx / (3 * P * per_panel);
    int rem = idx - t * (3 * P * per_panel);
    int g   = rem / per_panel;
    int rp  = rem - g * per_panel;
    int r   = rp >> 6;          // n within tile
    int kk  = rp & 63;          // k within panel
    int pass = g / P;
    int k    = (g - pass * P) * 64 + kk;
    int n    = t * 64 + r;
    float w = (k < K && n < N) ? W[(size_t)k * N + n] : 0.f;
    __nv_bfloat16 v;
    if (pass == 1) { __nv_bfloat16 h = __float2bfloat16(w); v = __float2bfloat16(w - __bfloat162float(h)); }
    else           { v = __float2bfloat16(w); }
    uint32_t off = sw128((uint32_t)r * 128 + kk * 2);
    char* base = (char*)out + ((size_t)(t * 3 * P + g)) * 8192;
    *reinterpret_cast<__nv_bfloat16*>(base + off) = v;
}

// ---------------- warp-MMA GEMM (split-bf16, 3-pass K-concat, k16-trimmed) ----------------
// C[M,N] = act(A'[M,splitK] @ W' + bias + resid). M%128==0.
// A' row: [hi(Kpad) | lo(Kpad)] bf16, stride=2*Kpad (Kpad = astride/2).
// NK16 = valid k16 steps per pass (<= 4*P). Only the valid k16s are computed;
// cp.async still loads full 64-col panels (always in-bounds of the 64-padded layout).
// grid = (NT, M/128); 256 threads; BM=128, BN=64; warps 4m x 2n, warp tile 32x32.
#define NSTAGE 4
#define A_STAGE_BYTES 16384
#define W_STAGE_BYTES 8192
#define AOFF 1024
#define WOFF (1024 + NSTAGE * A_STAGE_BYTES)
#define GEMM_SMEM (WOFF + NSTAGE * W_STAGE_BYTES)

__global__ void __launch_bounds__(256, 2)
gemm_mma(const __nv_bfloat16* __restrict__ A, int astride, int P, int NK16,
         const char* __restrict__ Wp,
         const float* __restrict__ bias, const float* __restrict__ resid,
         float* __restrict__ out, int N, int relu)
{
    extern __shared__ char smem[];
    const int tid  = threadIdx.x;
    const int wid  = tid >> 5;
    const int lane = tid & 31;
    const uint32_t sbase = smem_u32(smem);
    const int Kpad = astride >> 1;
    const int Pv = (NK16 + 3) >> 2;      // valid panels per pass
    const int PT = 3 * Pv;
    const size_t row0 = (size_t)blockIdx.y * 128;
    const int colbase = blockIdx.x * 64;

    auto issue_loads = [&](int j){
        int s = j & (NSTAGE - 1);
        int pass = j / Pv;
        int p = j - pass * Pv;
        uint32_t abase = sbase + AOFF + s * A_STAGE_BYTES;
        int srcoff = ((pass == 2) ? Kpad : 0) + p * 64;   // elements
        #pragma unroll
        for (int i = 0; i < 4; i++) {
            int idx = tid + 256 * i;
            int r = idx >> 3, c = idx & 7;
            const char* src = (const char*)(A + (row0 + r) * (size_t)astride + srcoff) + c * 16;
            cp16(abase + sw128((uint32_t)r * 128 + c * 16), src);
        }
        const char* wsrc = Wp + ((size_t)(blockIdx.x * 3 * P + pass * P + p)) * 8192;
        uint32_t wbase = sbase + WOFF + s * W_STAGE_BYTES;
        #pragma unroll
        for (int jj = 0; jj < 2; jj++) {
            int widx = tid + 256 * jj;
            cp16(wbase + widx * 16, wsrc + (size_t)widx * 16);
        }
        cp_commit();
    };

    issue_loads(0);
    if (PT > 1) issue_loads(1);
    if (PT > 2) issue_loads(2);

    const int mw = wid & 3;    // m block of 32
    const int nw = wid >> 2;   // n block of 32
    float acc[2][4][4];
    #pragma unroll
    for (int i = 0; i < 2; i++)
        #pragma unroll
        for (int j = 0; j < 4; j++)
            #pragma unroll
            for (int q = 0; q < 4; q++) acc[i][j][q] = 0.f;

    const int q8 = lane >> 3;     // 0..3
    const int r8 = lane & 7;      // 0..7

    for (int g = 0; g < PT; g++) {
        int s = g & (NSTAGE - 1);
        int rem = PT - 1 - g;
        if (rem >= 2)      asm volatile("cp.async.wait_group 2;" ::: "memory");
        else if (rem == 1) asm volatile("cp.async.wait_group 1;" ::: "memory");
        else               asm volatile("cp.async.wait_group 0;" ::: "memory");
        __syncthreads();

        // issue next panel into the stage freed at iteration g-1
        if (g + 3 < PT) issue_loads(g + 3);

        uint32_t abase = sbase + AOFF + s * A_STAGE_BYTES;
        uint32_t wbase = sbase + WOFF + s * W_STAGE_BYTES;

        int p = g - (g / Pv) * Pv;
        int ksn = NK16 - p * 4; if (ksn > 4) ksn = 4;

        auto do_ks = [&](int ks){
            const int kbyte = ks * 32;  // 16 bf16
            uint32_t a[2][4];
            #pragma unroll
            for (int tm = 0; tm < 2; tm++) {
                int arow = mw * 32 + tm * 16 + (q8 & 1) * 8 + r8;
                uint32_t off = sw128((uint32_t)arow * 128 + kbyte + (q8 >> 1) * 16);
                ldm4(a[tm][0], a[tm][1], a[tm][2], a[tm][3], abase + off);
            }
            uint32_t b[2][4];
            #pragma unroll
            for (int tb = 0; tb < 2; tb++) {
                int nrow = nw * 32 + tb * 16 + (q8 >> 1) * 8 + r8;
                uint32_t off = sw128((uint32_t)nrow * 128 + kbyte + (q8 & 1) * 16);
                ldm4(b[tb][0], b[tb][1], b[tb][2], b[tb][3], wbase + off);
            }
            #pragma unroll
            for (int tm = 0; tm < 2; tm++)
                #pragma unroll
                for (int tn = 0; tn < 4; tn++)
                    mma16816(acc[tm][tn], a[tm], b[tn >> 1][(tn & 1) * 2],
                             b[tn >> 1][(tn & 1) * 2 + 1]);
        };

        if (ksn == 4) {
            #pragma unroll
            for (int ks = 0; ks < 4; ks++) do_ks(ks);
        } else {
            for (int ks = 0; ks < ksn; ks++) do_ks(ks);
        }
    }

    // epilogue: acc[tm][tn][q] -> (m, n); (c, c+1) pairs contiguous, 8B-aligned.
    #pragma unroll
    for (int tm = 0; tm < 2; tm++) {
        #pragma unroll
        for (int half = 0; half < 2; half++) {
            size_t r = row0 + mw * 32 + tm * 16 + (lane >> 2) + half * 8;
            #pragma unroll
            for (int tn = 0; tn < 4; tn++) {
                int c = colbase + nw * 32 + tn * 8 + (lane & 3) * 2;
                if (c < N) {
                    float2 bv = *reinterpret_cast<const float2*>(&bias[c]);
                    float v0 = acc[tm][tn][half * 2]     + bv.x;
                    float v1 = acc[tm][tn][half * 2 + 1] + bv.y;
                    if (resid) {
                        float2 rv = *reinterpret_cast<const float2*>(&resid[r * N + c]);
                        v0 += rv.x; v1 += rv.y;
                    }
                    if (relu) { v0 = fmaxf(v0, 0.f); v1 = fmaxf(v1, 0.f); }
                    float2 q; q.x = v0; q.y = v1;
                    *reinterpret_cast<float2*>(&out[r * N + c]) = q;
                }
            }
        }
    }
}

// ---------------- A' builders ----------------
// conv_h0 writes only the 10 valid k16s (160 cols); cols [160,192) are never
// read by the trimmed GEMM.
#define KW_H0 160
__global__ void conv_h0(const float* __restrict__ v, const float* __restrict__ e,
                        const int* __restrict__ src, __nv_bfloat16* __restrict__ A)
{
    size_t idx = (size_t)blockIdx.x * 256 + threadIdx.x;
    if (idx >= (size_t)EEDGE * KW_H0) return;
    int r = (int)(idx / KW_H0), k = (int)(idx % KW_H0);
    float x = 0.f;
    if (k < NF)            x = v[(size_t)src[r] * (NF + 1) + k];
    else if (k < NF + EFE) x = e[(size_t)r * (EFE + 1) + (k - NF)];
    write_split(A + (size_t)r * 2 * KP_H0, KP_H0, k, x);
}

__global__ void conv_hv(const float* __restrict__ v, const float* __restrict__ mv,
                        __nv_bfloat16* __restrict__ A)
{
    size_t idx = (size_t)blockIdx.x * 256 + threadIdx.x;
    if (idx >= (size_t)NNODE * KP_HV) return;
    int r = (int)(idx / KP_HV), k = (int)(idx % KP_HV);
    float x = 0.f;
    if (k < NF)           x = v[(size_t)r * (NF + 1) + k];
    else if (k < NF + HH) x = mv[(size_t)r * HH + (k - NF)];
    write_split(A + (size_t)r * 2 * KP_HV, KP_HV, k, x);
}

// Kpad = storage stride/2; Kzero = write extent (16-aligned, >= Nin)
__global__ void conv_plain(const float* __restrict__ X, int Nin, int Kpad, int Kzero, int M,
                           __nv_bfloat16* __restrict__ A)
{
    size_t idx = (size_t)blockIdx.x * 256 + threadIdx.x;
    if (idx >= (size_t)M * Kzero) return;
    int r = (int)(idx / Kzero), k = (int)(idx % Kzero);
    float x = (k < Nin) ? X[(size_t)r * Nin + k] : 0.f;
    write_split(A + (size_t)r * 2 * Kpad, Kpad, k, x);
}

// mean over 32 nodes + concat globals -> A'_r1
__global__ void __launch_bounds__(256)
mean_conv(const float* __restrict__ hv, const float* __restrict__ gl,
          __nv_bfloat16* __restrict__ A)
{
    const int b = blockIdx.x;
    __nv_bfloat16* row = A + (size_t)b * 2 * KP_R1;
    for (int k = threadIdx.x; k < KP_R1; k += 256) {
        float x = 0.f;
        if (k < HH) {
            float s = 0.f;
            #pragma unroll 8
            for (int i = 0; i < NPER; i++) s += hv[(size_t)(b * NPER + i) * HH + k];
            x = s * (1.0f / NPER);
        } else if (k < HH + GG) {
            x = gl[(size_t)b * GG + (k - HH)];
        }
        write_split(row, KP_R1, k, x);
    }
}

// ---------------- per-graph message kernels ----------------
#define MSG_CH 100
// zero-pad extent for the loop A': only up to the last computed k16 (304)
#define KZ_L 4
__global__ void __launch_bounds__(256)
msg_kernel(const float* __restrict__ h, const int* __restrict__ src,
           const int* __restrict__ dst, __nv_bfloat16* __restrict__ A)
{
    __shared__ int s_src[64], s_dst[64];
    __shared__ float h_s[64 * MSG_CH];
    __shared__ float acc_s[32 * MSG_CH];
    const int b = blockIdx.x, tid = threadIdx.x;
    if (tid < 64) {
        s_src[tid] = src[b * 64 + tid] - b * 32;
        s_dst[tid] = dst[b * 64 + tid] - b * 32;
    }
    for (int c0 = 0; c0 < HH; c0 += MSG_CH) {
        __syncthreads();
        for (int idx = tid; idx < 64 * MSG_CH; idx += 256) {
            int e = idx / MSG_CH, c = idx - e * MSG_CH;
            h_s[idx] = h[(size_t)(b * 64 + e) * HH + c0 + c];
        }
        for (int idx = tid; idx < 32 * MSG_CH; idx += 256) acc_s[idx] = 0.f;
        __syncthreads();
        for (int idx = tid; idx < 64 * MSG_CH; idx += 256) {
            int e = idx / MSG_CH, c = idx - e * MSG_CH;
            atomicAdd(&acc_s[s_dst[e] * MSG_CH + c], h_s[idx]);
        }
        __syncthreads();
        for (int idx = tid; idx < 64 * MSG_CH; idx += 256) {
            int e = idx / MSG_CH, c = idx - e * MSG_CH;
            float x = acc_s[s_src[e] * MSG_CH + c] - h_s[(e ^ 1) * MSG_CH + c];
            write_split(A + (size_t)(b * 64 + e) * 2 * KP_L, KP_L, c0 + c, x);
        }
    }
    for (int idx = tid; idx < 64 * KZ_L; idx += 256) {
        int e = idx / KZ_L, k = HH + idx % KZ_L;
        __nv_bfloat16* row = A + (size_t)(b * 64 + e) * 2 * KP_L;
        row[k] = __float2bfloat16(0.f);
        row[KP_L + k] = __float2bfloat16(0.f);
    }
}

__global__ void __launch_bounds__(256)
mv_kernel(const float* __restrict__ h, const int* __restrict__ src,
          float* __restrict__ mv)
{
    __shared__ int s_src[64];
    __shared__ float h_s[64 * MSG_CH];
    __shared__ float acc_s[32 * MSG_CH];
    const int b = blockIdx.x, tid = threadIdx.x;
    if (tid < 64) s_src[tid] = src[b * 64 + tid] - b * 32;
    for (int c0 = 0; c0 < HH; c0 += MSG_CH) {
        __syncthreads();
        for (int idx = tid; idx < 64 * MSG_CH; idx += 256) {
            int e = idx / MSG_CH, c = idx - e * MSG_CH;
            h_s[idx] = h[(size_t)(b * 64 + e) * HH + c0 + c];
        }
        for (int idx = tid; idx < 32 * MSG_CH; idx += 256) acc_s[idx] = 0.f;
        __syncthreads();
        for (int idx = tid; idx < 64 * MSG_CH; idx += 256) {
            int e = idx / MSG_CH, c = idx - e * MSG_CH;
            atomicAdd(&acc_s[s_src[e] * MSG_CH + c], h_s[idx]);
        }
        __syncthreads();
        for (int idx = tid; idx < 32 * MSG_CH; idx += 256) {
            int n = idx / MSG_CH, c = idx - n * MSG_CH;
            mv[(size_t)(b * 32 + n) * HH + c0 + c] = acc_s[idx];
        }
    }
}

// ---------------- launch ----------------
extern "C" void kernel_launch(void* const* d_in, const int* in_sizes, int n_in,
                              void* d_out, int out_size)
{
    (void)in_sizes; (void)n_in; (void)out_size;
    const float* v   = (const float*)d_in[0];
    const float* e   = (const float*)d_in[1];
    const float* gl  = (const float*)d_in[2];
    const float* Wi  = (const float*)d_in[3];
    const float* bi  = (const float*)d_in[4];
    const float* Wm  = (const float*)d_in[5];
    const float* bm  = (const float*)d_in[6];
    const float* Wa  = (const float*)d_in[7];
    const float* ba  = (const float*)d_in[8];
    const float* Wr1 = (const float*)d_in[9];
    const float* br1 = (const float*)d_in[10];
    const float* Wr2 = (const float*)d_in[11];
    const float* br2 = (const float*)d_in[12];
    const float* Wr3 = (const float*)d_in[13];
    const float* br3 = (const float*)d_in[14];
    const int*   src = (const int*)d_in[15];
    const int*   dst = (const int*)d_in[16];
    float* out = (float*)d_out;

    float *h0, *hA, *hB, *mv, *hv, *r1, *r2;
    __nv_bfloat16 *Ae, *Ahv, *Ar1, *Ar2, *Ar3, *Wip, *Wmp, *Wap, *Wr1p, *Wr2p, *Wr3p;
    cudaGetSymbolAddress((void**)&h0, g_h0);
    cudaGetSymbolAddress((void**)&hA, g_hA);
    cudaGetSymbolAddress((void**)&hB, g_hB);
    cudaGetSymbolAddress((void**)&mv, g_mv);
    cudaGetSymbolAddress((void**)&hv, g_hv);
    cudaGetSymbolAddress((void**)&r1, g_r1);
    cudaGetSymbolAddress((void**)&r2, g_r2);
    cudaGetSymbolAddress((void**)&Ae,  g_Ae);
    cudaGetSymbolAddress((void**)&Ahv, g_Ahv);
    cudaGetSymbolAddress((void**)&Ar1, g_Ar1);
    cudaGetSymbolAddress((void**)&Ar2, g_Ar2);
    cudaGetSymbolAddress((void**)&Ar3, g_Ar3);
    cudaGetSymbolAddress((void**)&Wip, g_Wi);
    cudaGetSymbolAddress((void**)&Wmp, g_Wm);
    cudaGetSymbolAddress((void**)&Wap, g_Wa);
    cudaGetSymbolAddress((void**)&Wr1p, g_Wr1);
    cudaGetSymbolAddress((void**)&Wr2p, g_Wr2);
    cudaGetSymbolAddress((void**)&Wr3p, g_Wr3);

    cudaFuncSetAttribute(gemm_mma, cudaFuncAttributeMaxDynamicSharedMemorySize, GEMM_SMEM);

    // ---- weight prepacks ----
    auto pk = [&](const float* W, __nv_bfloat16* o, int K, int N, int P, int nt){
        int total = nt * 3 * P * 64 * 64;
        prepack_w<<<(total + 255) / 256, 256>>>(W, o, K, N, P, nt);
    };
    pk(Wi,  Wip,  NF + EFE, HH,  3, NT_H);
    pk(Wm,  Wmp,  HH,       HH,  5, NT_H);
    pk(Wa,  Wap,  NF + HH,  HH,  7, NT_H);
    pk(Wr1, Wr1p, HH + GG,  RR1, 8, NT_R1);
    pk(Wr2, Wr2p, RR1,      RR2, 9, NT_R2);
    pk(Wr3, Wr3p, RR2,      TT,  6, NT_R3);

    // ---- 1) h0 = relu([vv[src]|ee] @ Wi + bi) ----
    conv_h0<<<(int)(((size_t)EEDGE * KW_H0 + 255) / 256), 256>>>(v, e, src, Ae);
    gemm_mma<<<dim3(NT_H, EEDGE / 128), 256, GEMM_SMEM>>>(
        Ae, 2 * KP_H0, 3, 10, (const char*)Wip, bi, nullptr, h0, HH, 1);

    // ---- 2) message-passing layers ----
    const float* hin = h0;
    float* houts[3] = {hA, hB, hA};
    for (int l = 0; l < 3; l++) {
        msg_kernel<<<BB, 256>>>(hin, src, dst, Ae);
        gemm_mma<<<dim3(NT_H, EEDGE / 128), 256, GEMM_SMEM>>>(
            Ae, 2 * KP_L, 5, 19, (const char*)Wmp, bm, h0, houts[l], HH, 1);
        hin = houts[l];
    }

    // ---- 3) node aggregation + node MLP ----
    mv_kernel<<<BB, 256>>>(hin, src, mv);
    conv_hv<<<(int)(((size_t)NNODE * KP_HV + 255) / 256), 256>>>(v, mv, Ahv);
    gemm_mma<<<dim3(NT_H, NNODE / 128), 256, GEMM_SMEM>>>(
        Ahv, 2 * KP_HV, 7, 28, (const char*)Wap, ba, nullptr, hv, HH, 1);

    // ---- 4) graph mean + globals concat ----
    mean_conv<<<BB, 256>>>(hv, gl, Ar1);

    // ---- 5) readout MLP ----
    gemm_mma<<<dim3(NT_R1, BB / 128), 256, GEMM_SMEM>>>(
        Ar1, 2 * KP_R1, 8, 32, (const char*)Wr1p, br1, nullptr, r1, RR1, 1);
    conv_plain<<<(int)(((size_t)BB * 560 + 255) / 256), 256>>>(r1, RR1, KP_R2, 560, BB, Ar2);
    gemm_mma<<<dim3(NT_R2, BB / 128), 256, GEMM_SMEM>>>(
        Ar2, 2 * KP_R2, 9, 35, (const char*)Wr2p, br2, nullptr, r2, RR2, 1);
    conv_plain<<<(int)(((size_t)BB * KP_R3 + 255) / 256), 256>>>(r2, RR2, KP_R3, KP_R3, BB, Ar3);
    gemm_mma<<<dim3(NT_R3, BB / 128), 256, GEMM_SMEM>>>(
        Ar3, 2 * KP_R3, 6, 24, (const char*)Wr3p, br3, nullptr, out, TT, 0);
}

// round 11
// speedup vs baseline: 1.1555x; 1.1555x over previous
#include <cuda_runtime.h>
#include <cuda_bf16.h>
#include <cstdint>

// ---------------- problem constants ----------------
#define NF   133
#define EFE  14
#define HH   300
#define GG   200
#define TT   12
#define BB   4096
#define NPER 32
#define NNODE (BB*NPER)      // 131072
#define EEDGE (BB*64)        // 262144
#define RR1  550
#define RR2  378

// padded K per GEMM (storage, multiple of 64); P = K-panels of 64
#define KP_H0 192   // K=147, P=3
#define KP_L  320   // K=300, P=5
#define KP_HV 448   // K=433, P=7
#define KP_R1 512   // K=500, P=8
#define KP_R2 576   // K=550, P=9
#define KP_R3 384   // K=378, P=6

#define NT_H  5
#define NT_R1 9
#define NT_R2 6
#define NT_R3 1

// ---------------- scratch ----------------
__device__ float g_h0[(size_t)EEDGE*HH];
__device__ float g_mv[(size_t)NNODE*HH];
__device__ float g_hv[(size_t)NNODE*HH];
__device__ float g_r1[(size_t)BB*RR1];
__device__ float g_r2[(size_t)BB*RR2];

__device__ __nv_bfloat16 g_Ae [(size_t)EEDGE*2*KP_L];
__device__ __nv_bfloat16 g_Ae2[(size_t)EEDGE*2*KP_L];
__device__ __nv_bfloat16 g_Ahv[(size_t)NNODE*2*KP_HV];
__device__ __nv_bfloat16 g_Ar1[(size_t)BB*2*KP_R1];
__device__ __nv_bfloat16 g_Ar2[(size_t)BB*2*KP_R2];
__device__ __nv_bfloat16 g_Ar3[(size_t)BB*2*KP_R3];

// W panels: [ntile][3P][64 rows x 128B] swizzled bf16
__device__ __nv_bfloat16 g_Wi [(size_t)NT_H *9 *64*64];
__device__ __nv_bfloat16 g_Wm [(size_t)NT_H *15*64*64];
__device__ __nv_bfloat16 g_Wa [(size_t)NT_H *21*64*64];
__device__ __nv_bfloat16 g_Wr1[(size_t)NT_R1*24*64*64];
__device__ __nv_bfloat16 g_Wr2[(size_t)NT_R2*27*64*64];
__device__ __nv_bfloat16 g_Wr3[(size_t)NT_R3*18*64*64];

// ---------------- helpers ----------------
__device__ __forceinline__ uint32_t smem_u32(const void* p){
    uint32_t a;
    asm("{ .reg .u64 t; cvta.to.shared.u64 t, %1; cvt.u32.u64 %0, t; }" : "=r"(a) : "l"(p));
    return a;
}
__device__ __forceinline__ void cp16(uint32_t dst, const void* src){
    asm volatile("cp.async.cg.shared.global [%0], [%1], 16;" :: "r"(dst), "l"(src));
}
__device__ __forceinline__ void cp_commit(){
    asm volatile("cp.async.commit_group;" ::: "memory");
}
__device__ __forceinline__ void ldm4(uint32_t& r0, uint32_t& r1, uint32_t& r2, uint32_t& r3, uint32_t addr){
    asm volatile("ldmatrix.sync.aligned.m8n8.x4.shared.b16 {%0,%1,%2,%3}, [%4];"
                 : "=r"(r0), "=r"(r1), "=r"(r2), "=r"(r3) : "r"(addr));
}
__device__ __forceinline__ void mma16816(float* c, const uint32_t* a, uint32_t b0, uint32_t b1){
    asm volatile("mma.sync.aligned.m16n8k16.row.col.f32.bf16.bf16.f32 "
                 "{%0,%1,%2,%3}, {%4,%5,%6,%7}, {%8,%9}, {%0,%1,%2,%3};"
                 : "+f"(c[0]), "+f"(c[1]), "+f"(c[2]), "+f"(c[3])
                 : "r"(a[0]), "r"(a[1]), "r"(a[2]), "r"(a[3]), "r"(b0), "r"(b1));
}
__device__ __forceinline__ void write_split(__nv_bfloat16* row, int Kpad, int k, float x){
    __nv_bfloat16 h = __float2bfloat16(x);
    row[k] = h;
    row[Kpad + k] = __float2bfloat16(x - __bfloat162float(h));
}
__device__ __forceinline__ uint32_t sw128(uint32_t off){ return off ^ ((off >> 3) & 0x70); }

// ---------------- weight prepack ----------------
__global__ void prepack_w(const float* __restrict__ W, __nv_bfloat16* __restrict__ out,
                          int K, int N, int P, int ntiles)
{
    int idx = blockIdx.x * 256 + threadIdx.x;
    const int per_panel = 64 * 64;
    int total = ntiles * 3 * P * per_panel;
    if (idx >= total) return;
    int t   = idx / (3 * P * per_panel);
    int rem = idx - t * (3 * P * per_panel);
    int g   = rem / per_panel;
    int rp  = rem - g * per_panel;
    int r   = rp >> 6;
    int kk  = rp & 63;
    int pass = g / P;
    int k    = (g - pass * P) * 64 + kk;
    int n    = t * 64 + r;
    float w = (k < K && n < N) ? W[(size_t)k * N + n] : 0.f;
    __nv_bfloat16 v;
    if (pass == 1) { __nv_bfloat16 h = __float2bfloat16(w); v = __float2bfloat16(w - __bfloat162float(h)); }
    else           { v = __float2bfloat16(w); }
    uint32_t off = sw128((uint32_t)r * 128 + kk * 2);
    char* base = (char*)out + ((size_t)(t * 3 * P + g)) * 8192;
    *reinterpret_cast<__nv_bfloat16*>(base + off) = v;
}

// ---------------- warp-MMA GEMM with fused graph epilogues ----------------
// mode 0: plain  C = act(A@W + bias [+resid])
// mode 1: write h to out AND fused message -> A2 (split bf16, stride 2*KP_L)
// mode 2: no h write; fused message -> A2
// mode 3: no h write; fused per-graph src-segment-sum -> mvout (fp32, width HH)
// Fused modes require: M-rows are edges, 128 rows = 2 whole graphs, N == HH.
#define NSTAGE 4
#define A_STAGE_BYTES 16384
#define W_STAGE_BYTES 8192
#define AOFF 1024
#define WOFF (1024 + NSTAGE * A_STAGE_BYTES)
#define GEMM_SMEM (WOFF + NSTAGE * W_STAGE_BYTES)
#define HSS 66   // smem row stride (floats) for h tile / acc

__global__ void __launch_bounds__(256, 2)
gemm_mma(const __nv_bfloat16* __restrict__ A, int astride, int P,
         const char* __restrict__ Wp,
         const float* __restrict__ bias, const float* __restrict__ resid,
         float* __restrict__ out, int N, int relu,
         int mode, __nv_bfloat16* __restrict__ A2,
         const int* __restrict__ src_idx, const int* __restrict__ dst_idx,
         float* __restrict__ mvout)
{
    extern __shared__ char smem[];
    const int tid  = threadIdx.x;
    const int wid  = tid >> 5;
    const int lane = tid & 31;
    const uint32_t sbase = smem_u32(smem);
    const int PT = 3 * P;
    const size_t row0 = (size_t)blockIdx.y * 128;
    const int colbase = blockIdx.x * 64;

    auto issue_loads = [&](int g){
        int s = g & (NSTAGE - 1);
        uint32_t abase = sbase + AOFF + s * A_STAGE_BYTES;
        int srcoff = ((g < 2 * P) ? (g % P) : (g - P)) * 64;
        #pragma unroll
        for (int i = 0; i < 4; i++) {
            int idx = tid + 256 * i;
            int r = idx >> 3, c = idx & 7;
            const char* src = (const char*)(A + (row0 + r) * (size_t)astride + srcoff) + c * 16;
            cp16(abase + sw128((uint32_t)r * 128 + c * 16), src);
        }
        const char* wsrc = Wp + ((size_t)(blockIdx.x * PT + g)) * 8192;
        uint32_t wbase = sbase + WOFF + s * W_STAGE_BYTES;
        #pragma unroll
        for (int jj = 0; jj < 2; jj++) {
            int widx = tid + 256 * jj;
            cp16(wbase + widx * 16, wsrc + (size_t)widx * 16);
        }
        cp_commit();
    };

    issue_loads(0); issue_loads(1); issue_loads(2);

    const int mw = wid & 3;
    const int nw = wid >> 2;
    float acc[2][4][4];
    #pragma unroll
    for (int i = 0; i < 2; i++)
        #pragma unroll
        for (int j = 0; j < 4; j++)
            #pragma unroll
            for (int q = 0; q < 4; q++) acc[i][j][q] = 0.f;

    const int q8 = lane >> 3;
    const int r8 = lane & 7;

    for (int g = 0; g < PT; g++) {
        int s = g & (NSTAGE - 1);
        int rem = PT - 1 - g;
        if (rem >= 2)      asm volatile("cp.async.wait_group 2;" ::: "memory");
        else if (rem == 1) asm volatile("cp.async.wait_group 1;" ::: "memory");
        else               asm volatile("cp.async.wait_group 0;" ::: "memory");
        __syncthreads();

        if (g + 3 < PT) issue_loads(g + 3);

        uint32_t abase = sbase + AOFF + s * A_STAGE_BYTES;
        uint32_t wbase = sbase + WOFF + s * W_STAGE_BYTES;

        #pragma unroll
        for (int ks = 0; ks < 4; ks++) {
            const int kbyte = ks * 32;
            uint32_t a[2][4];
            #pragma unroll
            for (int tm = 0; tm < 2; tm++) {
                int arow = mw * 32 + tm * 16 + (q8 & 1) * 8 + r8;
                uint32_t off = sw128((uint32_t)arow * 128 + kbyte + (q8 >> 1) * 16);
                ldm4(a[tm][0], a[tm][1], a[tm][2], a[tm][3], abase + off);
            }
            uint32_t b[2][4];
            #pragma unroll
            for (int tb = 0; tb < 2; tb++) {
                int nrow = nw * 32 + tb * 16 + (q8 >> 1) * 8 + r8;
                uint32_t off = sw128((uint32_t)nrow * 128 + kbyte + (q8 & 1) * 16);
                ldm4(b[tb][0], b[tb][1], b[tb][2], b[tb][3], wbase + off);
            }
            #pragma unroll
            for (int tm = 0; tm < 2; tm++)
                #pragma unroll
                for (int tn = 0; tn < 4; tn++)
                    mma16816(acc[tm][tn], a[tm], b[tn >> 1][(tn & 1) * 2],
                             b[tn >> 1][(tn & 1) * 2 + 1]);
        }
    }

    // ---- epilogue: compute activated values (registers only) ----
    float vals[2][2][4][2];
    #pragma unroll
    for (int tm = 0; tm < 2; tm++) {
        #pragma unroll
        for (int half = 0; half < 2; half++) {
            size_t r = row0 + mw * 32 + tm * 16 + (lane >> 2) + half * 8;
            #pragma unroll
            for (int tn = 0; tn < 4; tn++) {
                int c = colbase + nw * 32 + tn * 8 + (lane & 3) * 2;
                float v0 = 0.f, v1 = 0.f;
                if (c < N) {
                    float2 bv = *reinterpret_cast<const float2*>(&bias[c]);
                    v0 = acc[tm][tn][half * 2]     + bv.x;
                    v1 = acc[tm][tn][half * 2 + 1] + bv.y;
                    if (resid) {
                        float2 rv = *reinterpret_cast<const float2*>(&resid[r * N + c]);
                        v0 += rv.x; v1 += rv.y;
                    }
                    if (relu) { v0 = fmaxf(v0, 0.f); v1 = fmaxf(v1, 0.f); }
                    if (mode <= 1 && out) {
                        float2 q; q.x = v0; q.y = v1;
                        *reinterpret_cast<float2*>(&out[r * N + c]) = q;
                    }
                }
                vals[tm][half][tn][0] = v0;
                vals[tm][half][tn][1] = v1;
            }
        }
    }
    if (mode == 0) return;

    // ---- fused graph epilogue: 2 whole graphs in this row-block ----
    int*   s_src = (int*)smem;              // [128]  (region [0,1024) is outside stages)
    int*   s_dst = s_src + 128;             // [128]
    float* hs    = (float*)(smem + 1024);   // [128][HSS]
    float* accm  = hs + 128 * HSS;          // [64][HSS]

    if (tid < 128) {
        s_src[tid] = src_idx[row0 + tid] - (int)(row0 >> 1);
        if (mode != 3) s_dst[tid] = dst_idx[row0 + tid] - (int)(row0 >> 1);
    }
    __syncthreads();   // all MMA smem reads done; safe to overwrite stages; s_idx visible

    #pragma unroll
    for (int tm = 0; tm < 2; tm++)
        #pragma unroll
        for (int half = 0; half < 2; half++) {
            int r_local = mw * 32 + tm * 16 + (lane >> 2) + half * 8;
            #pragma unroll
            for (int tn = 0; tn < 4; tn++) {
                int c_local = nw * 32 + tn * 8 + (lane & 3) * 2;
                float2 q; q.x = vals[tm][half][tn][0]; q.y = vals[tm][half][tn][1];
                *reinterpret_cast<float2*>(&hs[r_local * HSS + c_local]) = q;
            }
        }
    for (int i = tid; i < 64 * HSS; i += 256) accm[i] = 0.f;
    __syncthreads();

    const int* agg = (mode == 3) ? s_src : s_dst;
    #pragma unroll 4
    for (int i = tid; i < 128 * 64; i += 256) {
        int e2 = i >> 6, c2 = i & 63;
        atomicAdd(&accm[agg[e2] * HSS + c2], hs[e2 * HSS + c2]);
    }
    __syncthreads();

    if (mode == 3) {
        // mv rows: node base = row0/2, width N
        for (int i = tid; i < 64 * 32; i += 256) {
            int n = i >> 5, cp = (i & 31) << 1;
            int gc = colbase + cp;
            if (gc < N) {
                float2 q; q.x = accm[n * HSS + cp]; q.y = accm[n * HSS + cp + 1];
                *reinterpret_cast<float2*>(&mvout[((row0 >> 1) + n) * (size_t)N + gc]) = q;
            }
        }
    } else {
        // me[e][c] = acc[src[e]][c] - h[e^1][c]; split bf16 -> A2 (stride 2*KP_L)
        #pragma unroll 4
        for (int i = tid; i < 128 * 32; i += 256) {
            int e2 = i >> 5, cp = (i & 31) << 1;
            int sr = s_src[e2] * HSS;
            int rv = (e2 ^ 1) * HSS;
            float m0 = accm[sr + cp]     - hs[rv + cp];
            float m1 = accm[sr + cp + 1] - hs[rv + cp + 1];
            __nv_bfloat16 a0 = __float2bfloat16(m0), a1 = __float2bfloat16(m1);
            __nv_bfloat16 l0 = __float2bfloat16(m0 - __bfloat162float(a0));
            __nv_bfloat16 l1 = __float2bfloat16(m1 - __bfloat162float(a1));
            size_t base = (row0 + e2) * (size_t)(2 * KP_L) + colbase + cp;
            __nv_bfloat162 hv2; hv2.x = a0; hv2.y = a1;
            __nv_bfloat162 lv2; lv2.x = l0; lv2.y = l1;
            *reinterpret_cast<__nv_bfloat162*>(&A2[base])        = hv2;
            *reinterpret_cast<__nv_bfloat162*>(&A2[base + KP_L]) = lv2;
        }
    }
}

// ---------------- A' builders ----------------
__global__ void conv_h0(const float* __restrict__ v, const float* __restrict__ e,
                        const int* __restrict__ src, __nv_bfloat16* __restrict__ A)
{
    size_t idx = (size_t)blockIdx.x * 256 + threadIdx.x;
    if (idx >= (size_t)EEDGE * KP_H0) return;
    int r = (int)(idx / KP_H0), k = (int)(idx % KP_H0);
    float x = 0.f;
    if (k < NF)            x = v[(size_t)src[r] * (NF + 1) + k];
    else if (k < NF + EFE) x = e[(size_t)r * (EFE + 1) + (k - NF)];
    write_split(A + (size_t)r * 2 * KP_H0, KP_H0, k, x);
}

__global__ void conv_hv(const float* __restrict__ v, const float* __restrict__ mv,
                        __nv_bfloat16* __restrict__ A)
{
    size_t idx = (size_t)blockIdx.x * 256 + threadIdx.x;
    if (idx >= (size_t)NNODE * KP_HV) return;
    int r = (int)(idx / KP_HV), k = (int)(idx % KP_HV);
    float x = 0.f;
    if (k < NF)           x = v[(size_t)r * (NF + 1) + k];
    else if (k < NF + HH) x = mv[(size_t)r * HH + (k - NF)];
    write_split(A + (size_t)r * 2 * KP_HV, KP_HV, k, x);
}

__global__ void conv_plain(const float* __restrict__ X, int Nin, int Kpad, int M,
                           __nv_bfloat16* __restrict__ A)
{
    size_t idx = (size_t)blockIdx.x * 256 + threadIdx.x;
    if (idx >= (size_t)M * Kpad) return;
    int r = (int)(idx / Kpad), k = (int)(idx % Kpad);
    float x = (k < Nin) ? X[(size_t)r * Nin + k] : 0.f;
    write_split(A + (size_t)r * 2 * Kpad, Kpad, k, x);
}

__global__ void __launch_bounds__(256)
mean_conv(const float* __restrict__ hv, const float* __restrict__ gl,
          __nv_bfloat16* __restrict__ A)
{
    const int b = blockIdx.x;
    __nv_bfloat16* row = A + (size_t)b * 2 * KP_R1;
    for (int k = threadIdx.x; k < KP_R1; k += 256) {
        float x = 0.f;
        if (k < HH) {
            float s = 0.f;
            #pragma unroll 8
            for (int i = 0; i < NPER; i++) s += hv[(size_t)(b * NPER + i) * HH + k];
            x = s * (1.0f / NPER);
        } else if (k < HH + GG) {
            x = gl[(size_t)b * GG + (k - HH)];
        }
        write_split(row, KP_R1, k, x);
    }
}

// ---------------- launch ----------------
extern "C" void kernel_launch(void* const* d_in, const int* in_sizes, int n_in,
                              void* d_out, int out_size)
{
    (void)in_sizes; (void)n_in; (void)out_size;
    const float* v   = (const float*)d_in[0];
    const float* e   = (const float*)d_in[1];
    const float* gl  = (const float*)d_in[2];
    const float* Wi  = (const float*)d_in[3];
    const float* bi  = (const float*)d_in[4];
    const float* Wm  = (const float*)d_in[5];
    const float* bm  = (const float*)d_in[6];
    const float* Wa  = (const float*)d_in[7];
    const float* ba  = (const float*)d_in[8];
    const float* Wr1 = (const float*)d_in[9];
    const float* br1 = (const float*)d_in[10];
    const float* Wr2 = (const float*)d_in[11];
    const float* br2 = (const float*)d_in[12];
    const float* Wr3 = (const float*)d_in[13];
    const float* br3 = (const float*)d_in[14];
    const int*   src = (const int*)d_in[15];
    const int*   dst = (const int*)d_in[16];
    float* out = (float*)d_out;

    float *h0, *mv, *hv, *r1, *r2;
    __nv_bfloat16 *Ae, *Ae2, *Ahv, *Ar1, *Ar2, *Ar3, *Wip, *Wmp, *Wap, *Wr1p, *Wr2p, *Wr3p;
    cudaGetSymbolAddress((void**)&h0, g_h0);
    cudaGetSymbolAddress((void**)&mv, g_mv);
    cudaGetSymbolAddress((void**)&hv, g_hv);
    cudaGetSymbolAddress((void**)&r1, g_r1);
    cudaGetSymbolAddress((void**)&r2, g_r2);
    cudaGetSymbolAddress((void**)&Ae,  g_Ae);
    cudaGetSymbolAddress((void**)&Ae2, g_Ae2);
    cudaGetSymbolAddress((void**)&Ahv, g_Ahv);
    cudaGetSymbolAddress((void**)&Ar1, g_Ar1);
    cudaGetSymbolAddress((void**)&Ar2, g_Ar2);
    cudaGetSymbolAddress((void**)&Ar3, g_Ar3);
    cudaGetSymbolAddress((void**)&Wip, g_Wi);
    cudaGetSymbolAddress((void**)&Wmp, g_Wm);
    cudaGetSymbolAddress((void**)&Wap, g_Wa);
    cudaGetSymbolAddress((void**)&Wr1p, g_Wr1);
    cudaGetSymbolAddress((void**)&Wr2p, g_Wr2);
    cudaGetSymbolAddress((void**)&Wr3p, g_Wr3);

    cudaFuncSetAttribute(gemm_mma, cudaFuncAttributeMaxDynamicSharedMemorySize, GEMM_SMEM);

    auto pk = [&](const float* W, __nv_bfloat16* o, int K, int N, int P, int nt){
        int total = nt * 3 * P * 64 * 64;
        prepack_w<<<(total + 255) / 256, 256>>>(W, o, K, N, P, nt);
    };
    pk(Wi,  Wip,  NF + EFE, HH,  3, NT_H);
    pk(Wm,  Wmp,  HH,       HH,  5, NT_H);
    pk(Wa,  Wap,  NF + HH,  HH,  7, NT_H);
    pk(Wr1, Wr1p, HH + GG,  RR1, 8, NT_R1);
    pk(Wr2, Wr2p, RR1,      RR2, 9, NT_R2);
    pk(Wr3, Wr3p, RR2,      TT,  6, NT_R3);

    // ---- 1) h0 GEMM (mode 1: writes h0 + me1 -> Ae2) ----
    conv_h0<<<(int)(((size_t)EEDGE * KP_H0 + 255) / 256), 256>>>(v, e, src, Ae);
    gemm_mma<<<dim3(NT_H, EEDGE / 128), 256, GEMM_SMEM>>>(
        Ae, 2 * KP_H0, 3, (const char*)Wip, bi, nullptr, h0, HH, 1,
        1, Ae2, src, dst, nullptr);

    // ---- 2) message-passing layers (h never materialized) ----
    // L1: reads me1 (Ae2) -> me2 (Ae);  L2: reads me2 (Ae) -> me3 (Ae2);
    // L3: reads me3 (Ae2) -> mv (mode 3)
    gemm_mma<<<dim3(NT_H, EEDGE / 128), 256, GEMM_SMEM>>>(
        Ae2, 2 * KP_L, 5, (const char*)Wmp, bm, h0, nullptr, HH, 1,
        2, Ae, src, dst, nullptr);
    gemm_mma<<<dim3(NT_H, EEDGE / 128), 256, GEMM_SMEM>>>(
        Ae, 2 * KP_L, 5, (const char*)Wmp, bm, h0, nullptr, HH, 1,
        2, Ae2, src, dst, nullptr);
    gemm_mma<<<dim3(NT_H, EEDGE / 128), 256, GEMM_SMEM>>>(
        Ae2, 2 * KP_L, 5, (const char*)Wmp, bm, h0, nullptr, HH, 1,
        3, nullptr, src, dst, mv);

    // ---- 3) node MLP ----
    conv_hv<<<(int)(((size_t)NNODE * KP_HV + 255) / 256), 256>>>(v, mv, Ahv);
    gemm_mma<<<dim3(NT_H, NNODE / 128), 256, GEMM_SMEM>>>(
        Ahv, 2 * KP_HV, 7, (const char*)Wap, ba, nullptr, hv, HH, 1,
        0, nullptr, nullptr, nullptr, nullptr);

    // ---- 4) graph mean + globals concat ----
    mean_conv<<<BB, 256>>>(hv, gl, Ar1);

    // ---- 5) readout MLP ----
    gemm_mma<<<dim3(NT_R1, BB / 128), 256, GEMM_SMEM>>>(
        Ar1, 2 * KP_R1, 8, (const char*)Wr1p, br1, nullptr, r1, RR1, 1,
        0, nullptr, nullptr, nullptr, nullptr);
    conv_plain<<<(int)(((size_t)BB * KP_R2 + 255) / 256), 256>>>(r1, RR1, KP_R2, BB, Ar2);
    gemm_mma<<<dim3(NT_R2, BB / 128), 256, GEMM_SMEM>>>(
        Ar2, 2 * KP_R2, 9, (const char*)Wr2p, br2, nullptr, r2, RR2, 1,
        0, nullptr, nullptr, nullptr, nullptr);
    conv_plain<<<(int)(((size_t)BB * KP_R3 + 255) / 256), 256>>>(r2, RR2, KP_R3, BB, Ar3);
    gemm_mma<<<dim3(NT_R3, BB / 128), 256, GEMM_SMEM>>>(
        Ar3, 2 * KP_R3, 6, (const char*)Wr3p, br3, nullptr, out, TT, 0,
        0, nullptr, nullptr, nullptr, nullptr);
}

// round 13
// speedup vs baseline: 1.2133x; 1.0500x over previous
#include <cuda_runtime.h>
#include <cuda_bf16.h>
#include <cstdint>

// ---------------- problem constants ----------------
#define NF   133
#define EFE  14
#define HH   300
#define GG   200
#define TT   12
#define BB   4096
#define NPER 32
#define NNODE (BB*NPER)      // 131072
#define EEDGE (BB*64)        // 262144
#define RR1  550
#define RR2  378

// padded K per GEMM (storage, multiple of 64); P = K-panels of 64
#define KP_H0 192   // K=147, P=3
#define KP_L  320   // K=300, P=5
#define KP_HV 448   // K=444 logical (vv 0..133 | gap ..144 | mv ..444), P=7
#define KP_R1 512   // K=500, P=8
#define KP_R2 576   // K=550, P=9
#define KP_R3 384   // K=378, P=6

#define MV_OFF 144  // 16-aligned start of mv block inside A_hv
#define WA_GAP 11   // gap length (144-133)

#define NT_H  5
#define NT_R1 9
#define NT_R2 6
#define NT_R3 1

// ---------------- scratch ----------------
__device__ float g_h0[(size_t)EEDGE*HH];
__device__ float g_r1[(size_t)BB*RR1];
__device__ float g_r2[(size_t)BB*RR2];

__device__ __nv_bfloat16 g_Ae [(size_t)EEDGE*2*KP_L];
__device__ __nv_bfloat16 g_Ae2[(size_t)EEDGE*2*KP_L];
__device__ __nv_bfloat16 g_Ahv[(size_t)NNODE*2*KP_HV];
__device__ __nv_bfloat16 g_Ar1[(size_t)BB*2*KP_R1];
__device__ __nv_bfloat16 g_Ar2[(size_t)BB*2*KP_R2];
__device__ __nv_bfloat16 g_Ar3[(size_t)BB*2*KP_R3];

// W panels: [ntile][3P][64 rows x 128B] swizzled bf16
__device__ __nv_bfloat16 g_Wi [(size_t)NT_H *9 *64*64];
__device__ __nv_bfloat16 g_Wm [(size_t)NT_H *15*64*64];
__device__ __nv_bfloat16 g_Wa [(size_t)NT_H *21*64*64];
__device__ __nv_bfloat16 g_Wr1[(size_t)NT_R1*24*64*64];
__device__ __nv_bfloat16 g_Wr2[(size_t)NT_R2*27*64*64];
__device__ __nv_bfloat16 g_Wr3[(size_t)NT_R3*18*64*64];

// ---------------- helpers ----------------
__device__ __forceinline__ uint32_t smem_u32(const void* p){
    uint32_t a;
    asm("{ .reg .u64 t; cvta.to.shared.u64 t, %1; cvt.u32.u64 %0, t; }" : "=r"(a) : "l"(p));
    return a;
}
__device__ __forceinline__ void cp16(uint32_t dst, const void* src){
    asm volatile("cp.async.cg.shared.global [%0], [%1], 16;" :: "r"(dst), "l"(src));
}
__device__ __forceinline__ void cp_commit(){
    asm volatile("cp.async.commit_group;" ::: "memory");
}
__device__ __forceinline__ void ldm4(uint32_t& r0, uint32_t& r1, uint32_t& r2, uint32_t& r3, uint32_t addr){
    asm volatile("ldmatrix.sync.aligned.m8n8.x4.shared.b16 {%0,%1,%2,%3}, [%4];"
                 : "=r"(r0), "=r"(r1), "=r"(r2), "=r"(r3) : "r"(addr));
}
__device__ __forceinline__ void mma16816(float* c, const uint32_t* a, uint32_t b0, uint32_t b1){
    asm volatile("mma.sync.aligned.m16n8k16.row.col.f32.bf16.bf16.f32 "
                 "{%0,%1,%2,%3}, {%4,%5,%6,%7}, {%8,%9}, {%0,%1,%2,%3};"
                 : "+f"(c[0]), "+f"(c[1]), "+f"(c[2]), "+f"(c[3])
                 : "r"(a[0]), "r"(a[1]), "r"(a[2]), "r"(a[3]), "r"(b0), "r"(b1));
}
__device__ __forceinline__ void write_split(__nv_bfloat16* row, int Kpad, int k, float x){
    __nv_bfloat16 h = __float2bfloat16(x);
    row[k] = h;
    row[Kpad + k] = __float2bfloat16(x - __bfloat162float(h));
}
__device__ __forceinline__ void split_pair(float m0, float m1, __nv_bfloat16* base, int Kpad){
    __nv_bfloat16 a0 = __float2bfloat16(m0), a1 = __float2bfloat16(m1);
    __nv_bfloat162 hv2; hv2.x = a0; hv2.y = a1;
    __nv_bfloat162 lv2;
    lv2.x = __float2bfloat16(m0 - __bfloat162float(a0));
    lv2.y = __float2bfloat16(m1 - __bfloat162float(a1));
    *reinterpret_cast<__nv_bfloat162*>(base)        = hv2;
    *reinterpret_cast<__nv_bfloat162*>(base + Kpad) = lv2;
}
__device__ __forceinline__ uint32_t sw128(uint32_t off){ return off ^ ((off >> 3) & 0x70); }

// ---------------- weight prepack ----------------
// gap remap: weight row keff = k < gap_start ? k : k - gap_len; rows in
// [gap_start, gap_start+gap_len) produce zero. (gap 0/0 = identity.)
__global__ void prepack_w(const float* __restrict__ W, __nv_bfloat16* __restrict__ out,
                          int K, int N, int P, int ntiles, int gap_start, int gap_len)
{
    int idx = blockIdx.x * 256 + threadIdx.x;
    const int per_panel = 64 * 64;
    int total = ntiles * 3 * P * per_panel;
    if (idx >= total) return;
    int t   = idx / (3 * P * per_panel);
    int rem = idx - t * (3 * P * per_panel);
    int g   = rem / per_panel;
    int rp  = rem - g * per_panel;
    int r   = rp >> 6;
    int kk  = rp & 63;
    int pass = g / P;
    int k    = (g - pass * P) * 64 + kk;
    int n    = t * 64 + r;
    int keff = (k < gap_start) ? k : k - gap_len;
    bool inGap = (k >= gap_start) && (k < gap_start + gap_len);
    float w = (!inGap && keff < K && n < N) ? W[(size_t)keff * N + n] : 0.f;
    __nv_bfloat16 v;
    if (pass == 1) { __nv_bfloat16 h = __float2bfloat16(w); v = __float2bfloat16(w - __bfloat162float(h)); }
    else           { v = __float2bfloat16(w); }
    uint32_t off = sw128((uint32_t)r * 128 + kk * 2);
    char* base = (char*)out + ((size_t)(t * 3 * P + g)) * 8192;
    *reinterpret_cast<__nv_bfloat16*>(base + off) = v;
}

// ---------------- warp-MMA GEMM with fused graph epilogues ----------------
// mode 0: plain  C = act(A@W + bias [+resid])
// mode 1: write h to out AND fused message -> A2 (split bf16, Kpad=a2_kpad)
// mode 2: no h write; fused message -> A2
// mode 3: no h write; fused src-segment-sum -> split bf16 into A2 at col MV_OFF
//         (rows = nodes row0/2+n, Kpad=a2_kpad)
// mode 4: no h write; per-graph mean (128 rows = 4 graphs of 32) -> split bf16
//         into A2 rows row0/32+gb, cols colbase+c (<HH), Kpad=a2_kpad
#define NSTAGE 4
#define A_STAGE_BYTES 16384
#define W_STAGE_BYTES 8192
#define AOFF 1024
#define WOFF (1024 + NSTAGE * A_STAGE_BYTES)
#define GEMM_SMEM (WOFF + NSTAGE * W_STAGE_BYTES)
#define HSS 66

__global__ void __launch_bounds__(256, 2)
gemm_mma(const __nv_bfloat16* __restrict__ A, int astride, int P,
         const char* __restrict__ Wp,
         const float* __restrict__ bias, const float* __restrict__ resid,
         float* __restrict__ out, int N, int relu,
         int mode, __nv_bfloat16* __restrict__ A2, int a2_kpad,
         const int* __restrict__ src_idx, const int* __restrict__ dst_idx)
{
    extern __shared__ char smem[];
    const int tid  = threadIdx.x;
    const int wid  = tid >> 5;
    const int lane = tid & 31;
    const uint32_t sbase = smem_u32(smem);
    const int PT = 3 * P;
    const size_t row0 = (size_t)blockIdx.y * 128;
    const int colbase = blockIdx.x * 64;

    auto issue_loads = [&](int g){
        int s = g & (NSTAGE - 1);
        uint32_t abase = sbase + AOFF + s * A_STAGE_BYTES;
        int srcoff = ((g < 2 * P) ? (g % P) : (g - P)) * 64;
        #pragma unroll
        for (int i = 0; i < 4; i++) {
            int idx = tid + 256 * i;
            int r = idx >> 3, c = idx & 7;
            const char* src = (const char*)(A + (row0 + r) * (size_t)astride + srcoff) + c * 16;
            cp16(abase + sw128((uint32_t)r * 128 + c * 16), src);
        }
        const char* wsrc = Wp + ((size_t)(blockIdx.x * PT + g)) * 8192;
        uint32_t wbase = sbase + WOFF + s * W_STAGE_BYTES;
        #pragma unroll
        for (int jj = 0; jj < 2; jj++) {
            int widx = tid + 256 * jj;
            cp16(wbase + widx * 16, wsrc + (size_t)widx * 16);
        }
        cp_commit();
    };

    issue_loads(0); issue_loads(1); issue_loads(2);

    const int mw = wid & 3;
    const int nw = wid >> 2;
    float acc[2][4][4];
    #pragma unroll
    for (int i = 0; i < 2; i++)
        #pragma unroll
        for (int j = 0; j < 4; j++)
            #pragma unroll
            for (int q = 0; q < 4; q++) acc[i][j][q] = 0.f;

    const int q8 = lane >> 3;
    const int r8 = lane & 7;

    for (int g = 0; g < PT; g++) {
        int s = g & (NSTAGE - 1);
        int rem = PT - 1 - g;
        if (rem >= 2)      asm volatile("cp.async.wait_group 2;" ::: "memory");
        else if (rem == 1) asm volatile("cp.async.wait_group 1;" ::: "memory");
        else               asm volatile("cp.async.wait_group 0;" ::: "memory");
        __syncthreads();

        if (g + 3 < PT) issue_loads(g + 3);

        uint32_t abase = sbase + AOFF + s * A_STAGE_BYTES;
        uint32_t wbase = sbase + WOFF + s * W_STAGE_BYTES;

        #pragma unroll
        for (int ks = 0; ks < 4; ks++) {
            const int kbyte = ks * 32;
            uint32_t a[2][4];
            #pragma unroll
            for (int tm = 0; tm < 2; tm++) {
                int arow = mw * 32 + tm * 16 + (q8 & 1) * 8 + r8;
                uint32_t off = sw128((uint32_t)arow * 128 + kbyte + (q8 >> 1) * 16);
                ldm4(a[tm][0], a[tm][1], a[tm][2], a[tm][3], abase + off);
            }
            uint32_t b[2][4];
            #pragma unroll
            for (int tb = 0; tb < 2; tb++) {
                int nrow = nw * 32 + tb * 16 + (q8 >> 1) * 8 + r8;
                uint32_t off = sw128((uint32_t)nrow * 128 + kbyte + (q8 & 1) * 16);
                ldm4(b[tb][0], b[tb][1], b[tb][2], b[tb][3], wbase + off);
            }
            #pragma unroll
            for (int tm = 0; tm < 2; tm++)
                #pragma unroll
                for (int tn = 0; tn < 4; tn++)
                    mma16816(acc[tm][tn], a[tm], b[tn >> 1][(tn & 1) * 2],
                             b[tn >> 1][(tn & 1) * 2 + 1]);
        }
    }

    // ---- epilogue: activated values in registers ----
    float vals[2][2][4][2];
    #pragma unroll
    for (int tm = 0; tm < 2; tm++) {
        #pragma unroll
        for (int half = 0; half < 2; half++) {
            size_t r = row0 + mw * 32 + tm * 16 + (lane >> 2) + half * 8;
            #pragma unroll
            for (int tn = 0; tn < 4; tn++) {
                int c = colbase + nw * 32 + tn * 8 + (lane & 3) * 2;
                float v0 = 0.f, v1 = 0.f;
                if (c < N) {
                    float2 bv = *reinterpret_cast<const float2*>(&bias[c]);
                    v0 = acc[tm][tn][half * 2]     + bv.x;
                    v1 = acc[tm][tn][half * 2 + 1] + bv.y;
                    if (resid) {
                        float2 rv = *reinterpret_cast<const float2*>(&resid[r * N + c]);
                        v0 += rv.x; v1 += rv.y;
                    }
                    if (relu) { v0 = fmaxf(v0, 0.f); v1 = fmaxf(v1, 0.f); }
                    if (mode <= 1 && out) {
                        float2 q; q.x = v0; q.y = v1;
                        *reinterpret_cast<float2*>(&out[r * N + c]) = q;
                    }
                }
                vals[tm][half][tn][0] = v0;
                vals[tm][half][tn][1] = v1;
            }
        }
    }
    if (mode == 0) return;

    // ---- fused graph epilogue ----
    int*   s_src = (int*)smem;
    int*   s_dst = s_src + 128;
    float* hs    = (float*)(smem + 1024);
    float* accm  = hs + 128 * HSS;

    if (mode <= 3 && tid < 128) {
        s_src[tid] = src_idx[row0 + tid] - (int)(row0 >> 1);
        if (mode != 3) s_dst[tid] = dst_idx[row0 + tid] - (int)(row0 >> 1);
    }
    __syncthreads();   // MMA smem reads done; stages reusable; indices visible

    #pragma unroll
    for (int tm = 0; tm < 2; tm++)
        #pragma unroll
        for (int half = 0; half < 2; half++) {
            int r_local = mw * 32 + tm * 16 + (lane >> 2) + half * 8;
            #pragma unroll
            for (int tn = 0; tn < 4; tn++) {
                int c_local = nw * 32 + tn * 8 + (lane & 3) * 2;
                float2 q; q.x = vals[tm][half][tn][0]; q.y = vals[tm][half][tn][1];
                *reinterpret_cast<float2*>(&hs[r_local * HSS + c_local]) = q;
            }
        }

    if (mode == 4) {
        __syncthreads();
        // 128 rows = 4 graphs of 32 nodes; mean per graph column
        int gb = tid >> 6, c = tid & 63;
        int gc = colbase + c;
        if (gc < HH) {
            float s = 0.f;
            #pragma unroll 8
            for (int i = 0; i < 32; i++) s += hs[(gb * 32 + i) * HSS + c];
            write_split(A2 + ((row0 >> 5) + gb) * (size_t)(2 * a2_kpad), a2_kpad,
                        gc, s * (1.0f / NPER));
        }
        return;
    }

    for (int i = tid; i < 64 * HSS; i += 256) accm[i] = 0.f;
    __syncthreads();

    const int* agg = (mode == 3) ? s_src : s_dst;
    #pragma unroll 4
    for (int i = tid; i < 128 * 64; i += 256) {
        int e2 = i >> 6, c2 = i & 63;
        atomicAdd(&accm[agg[e2] * HSS + c2], hs[e2 * HSS + c2]);
    }
    __syncthreads();

    if (mode == 3) {
        // node segment-sum -> split bf16 into A_hv at col MV_OFF+gc
        for (int i = tid; i < 64 * 32; i += 256) {
            int n = i >> 5, cp = (i & 31) << 1;
            int gc = colbase + cp;
            if (gc < HH) {
                size_t base = ((row0 >> 1) + n) * (size_t)(2 * a2_kpad) + MV_OFF + gc;
                split_pair(accm[n * HSS + cp], accm[n * HSS + cp + 1], A2 + base, a2_kpad);
            }
        }
    } else {
        // me[e][c] = acc[src[e]][c] - h[e^1][c]
        #pragma unroll 4
        for (int i = tid; i < 128 * 32; i += 256) {
            int e2 = i >> 5, cp = (i & 31) << 1;
            int sr = s_src[e2] * HSS;
            int rv = (e2 ^ 1) * HSS;
            size_t base = (row0 + e2) * (size_t)(2 * a2_kpad) + colbase + cp;
            split_pair(accm[sr + cp]     - hs[rv + cp],
                       accm[sr + cp + 1] - hs[rv + cp + 1], A2 + base, a2_kpad);
        }
    }
}

// ---------------- A' builders ----------------
__global__ void conv_h0(const float* __restrict__ v, const float* __restrict__ e,
                        const int* __restrict__ src, __nv_bfloat16* __restrict__ A)
{
    size_t idx = (size_t)blockIdx.x * 256 + threadIdx.x;
    if (idx >= (size_t)EEDGE * KP_H0) return;
    int r = (int)(idx / KP_H0), k = (int)(idx % KP_H0);
    float x = 0.f;
    if (k < NF)            x = v[(size_t)src[r] * (NF + 1) + k];
    else if (k < NF + EFE) x = e[(size_t)r * (EFE + 1) + (k - NF)];
    write_split(A + (size_t)r * 2 * KP_H0, KP_H0, k, x);
}

// vv + gap + tail-pad columns of A_hv: k in [0,MV_OFF) U [MV_OFF+HH, KP_HV)
#define VV_COLS (MV_OFF + (KP_HV - MV_OFF - HH))   // 144 + 4 = 148
__global__ void conv_vv(const float* __restrict__ v, __nv_bfloat16* __restrict__ A)
{
    size_t idx = (size_t)blockIdx.x * 256 + threadIdx.x;
    if (idx >= (size_t)NNODE * VV_COLS) return;
    int r = (int)(idx / VV_COLS), kc = (int)(idx % VV_COLS);
    int k = (kc < MV_OFF) ? kc : (MV_OFF + HH + (kc - MV_OFF));
    float x = (k < NF) ? v[(size_t)r * (NF + 1) + k] : 0.f;
    write_split(A + (size_t)r * 2 * KP_HV, KP_HV, k, x);
}

// globals + padding columns of Ar1: k in [HH, KP_R1)
__global__ void glob_conv(const float* __restrict__ gl, __nv_bfloat16* __restrict__ A)
{
    size_t idx = (size_t)blockIdx.x * 256 + threadIdx.x;
    const int W = KP_R1 - HH;   // 212
    if (idx >= (size_t)BB * W) return;
    int b = (int)(idx / W), k = HH + (int)(idx % W);
    float x = (k < HH + GG) ? gl[(size_t)b * GG + (k - HH)] : 0.f;
    write_split(A + (size_t)b * 2 * KP_R1, KP_R1, k, x);
}

__global__ void conv_plain(const float* __restrict__ X, int Nin, int Kpad, int M,
                           __nv_bfloat16* __restrict__ A)
{
    size_t idx = (size_t)blockIdx.x * 256 + threadIdx.x;
    if (idx >= (size_t)M * Kpad) return;
    int r = (int)(idx / Kpad), k = (int)(idx % Kpad);
    float x = (k < Nin) ? X[(size_t)r * Nin + k] : 0.f;
    write_split(A + (size_t)r * 2 * Kpad, Kpad, k, x);
}

// ---------------- launch ----------------
extern "C" void kernel_launch(void* const* d_in, const int* in_sizes, int n_in,
                              void* d_out, int out_size)
{
    (void)in_sizes; (void)n_in; (void)out_size;
    const float* v   = (const float*)d_in[0];
    const float* e   = (const float*)d_in[1];
    const float* gl  = (const float*)d_in[2];
    const float* Wi  = (const float*)d_in[3];
    const float* bi  = (const float*)d_in[4];
    const float* Wm  = (const float*)d_in[5];
    const float* bm  = (const float*)d_in[6];
    const float* Wa  = (const float*)d_in[7];
    const float* ba  = (const float*)d_in[8];
    const float* Wr1 = (const float*)d_in[9];
    const float* br1 = (const float*)d_in[10];
    const float* Wr2 = (const float*)d_in[11];
    const float* br2 = (const float*)d_in[12];
    const float* Wr3 = (const float*)d_in[13];
    const float* br3 = (const float*)d_in[14];
    const int*   src = (const int*)d_in[15];
    const int*   dst = (const int*)d_in[16];
    float* out = (float*)d_out;

    float *h0, *r1, *r2;
    __nv_bfloat16 *Ae, *Ae2, *Ahv, *Ar1, *Ar2, *Ar3, *Wip, *Wmp, *Wap, *Wr1p, *Wr2p, *Wr3p;
    cudaGetSymbolAddress((void**)&h0, g_h0);
    cudaGetSymbolAddress((void**)&r1, g_r1);
    cudaGetSymbolAddress((void**)&r2, g_r2);
    cudaGetSymbolAddress((void**)&Ae,  g_Ae);
    cudaGetSymbolAddress((void**)&Ae2, g_Ae2);
    cudaGetSymbolAddress((void**)&Ahv, g_Ahv);
    cudaGetSymbolAddress((void**)&Ar1, g_Ar1);
    cudaGetSymbolAddress((void**)&Ar2, g_Ar2);
    cudaGetSymbolAddress((void**)&Ar3, g_Ar3);
    cudaGetSymbolAddress((void**)&Wip, g_Wi);
    cudaGetSymbolAddress((void**)&Wmp, g_Wm);
    cudaGetSymbolAddress((void**)&Wap, g_Wa);
    cudaGetSymbolAddress((void**)&Wr1p, g_Wr1);
    cudaGetSymbolAddress((void**)&Wr2p, g_Wr2);
    cudaGetSymbolAddress((void**)&Wr3p, g_Wr3);

    cudaFuncSetAttribute(gemm_mma, cudaFuncAttributeMaxDynamicSharedMemorySize, GEMM_SMEM);

    auto pk = [&](const float* W, __nv_bfloat16* o, int K, int N, int P, int nt,
                  int gs, int glen){
        int total = nt * 3 * P * 64 * 64;
        prepack_w<<<(total + 255) / 256, 256>>>(W, o, K, N, P, nt, gs, glen);
    };
    pk(Wi,  Wip,  NF + EFE, HH,  3, NT_H,  0, 0);
    pk(Wm,  Wmp,  HH,       HH,  5, NT_H,  0, 0);
    pk(Wa,  Wap,  NF + HH,  HH,  7, NT_H,  NF, WA_GAP);   // row gap at 133..144
    pk(Wr1, Wr1p, HH + GG,  RR1, 8, NT_R1, 0, 0);
    pk(Wr2, Wr2p, RR1,      RR2, 9, NT_R2, 0, 0);
    pk(Wr3, Wr3p, RR2,      TT,  6, NT_R3, 0, 0);

    // A_hv static columns (vv | gap | tail pad) — once, early
    conv_vv<<<(int)(((size_t)NNODE * VV_COLS + 255) / 256), 256>>>(v, Ahv);
    // Ar1 globals/pad columns
    glob_conv<<<(int)(((size_t)BB * (KP_R1 - HH) + 255) / 256), 256>>>(gl, Ar1);

    // ---- 1) h0 GEMM (mode 1: writes h0 + me1 -> Ae2) ----
    conv_h0<<<(int)(((size_t)EEDGE * KP_H0 + 255) / 256), 256>>>(v, e, src, Ae);
    gemm_mma<<<dim3(NT_H, EEDGE / 128), 256, GEMM_SMEM>>>(
        Ae, 2 * KP_H0, 3, (const char*)Wip, bi, nullptr, h0, HH, 1,
        1, Ae2, KP_L, src, dst);

    // ---- 2) message-passing layers (h never materialized) ----
    gemm_mma<<<dim3(NT_H, EEDGE / 128), 256, GEMM_SMEM>>>(
        Ae2, 2 * KP_L, 5, (const char*)Wmp, bm, h0, nullptr, HH, 1,
        2, Ae, KP_L, src, dst);
    gemm_mma<<<dim3(NT_H, EEDGE / 128), 256, GEMM_SMEM>>>(
        Ae, 2 * KP_L, 5, (const char*)Wmp, bm, h0, nullptr, HH, 1,
        2, Ae2, KP_L, src, dst);
    // L3: segment-sum -> split bf16 mv columns of A_hv
    gemm_mma<<<dim3(NT_H, EEDGE / 128), 256, GEMM_SMEM>>>(
        Ae2, 2 * KP_L, 5, (const char*)Wmp, bm, h0, nullptr, HH, 1,
        3, Ahv, KP_HV, src, dst);

    // ---- 3) node MLP (mode 4: per-graph mean -> split bf16 into Ar1) ----
    gemm_mma<<<dim3(NT_H, NNODE / 128), 256, GEMM_SMEM>>>(
        Ahv, 2 * KP_HV, 7, (const char*)Wap, ba, nullptr, nullptr, HH, 1,
        4, Ar1, KP_R1, nullptr, nullptr);

    // ---- 4) readout MLP ----
    gemm_mma<<<dim3(NT_R1, BB / 128), 256, GEMM_SMEM>>>(
        Ar1, 2 * KP_R1, 8, (const char*)Wr1p, br1, nullptr, r1, RR1, 1,
        0, nullptr, 0, nullptr, nullptr);
    conv_plain<<<(int)(((size_t)BB * KP_R2 + 255) / 256), 256>>>(r1, RR1, KP_R2, BB, Ar2);
    gemm_mma<<<dim3(NT_R2, BB / 128), 256, GEMM_SMEM>>>(
        Ar2, 2 * KP_R2, 9, (const char*)Wr2p, br2, nullptr, r2, RR2, 1,
        0, nullptr, 0, nullptr, nullptr);
    conv_plain<<<(int)(((size_t)BB * KP_R3 + 255) / 256), 256>>>(r2, RR2, KP_R3, BB, Ar3);
    gemm_mma<<<dim3(NT_R3, BB / 128), 256, GEMM_SMEM>>>(
        Ar3, 2 * KP_R3, 6, (const char*)Wr3p, br3, nullptr, out, TT, 0,
        0, nullptr, 0, nullptr, nullptr);
}

// round 14
// speedup vs baseline: 1.2529x; 1.0326x over previous
#include <cuda_runtime.h>
#include <cuda_bf16.h>
#include <cstdint>

// ---------------- problem constants ----------------
#define NF   133
#define EFE  14
#define HH   300
#define GG   200
#define TT   12
#define BB   4096
#define NPER 32
#define NNODE (BB*NPER)      // 131072
#define EEDGE (BB*64)        // 262144
#define RR1  550
#define RR2  378

// padded K per GEMM (storage, multiple of 64); PS = storage K-panels of 64
#define KP_H0 192   // K=147,  PS=3, NK16=10
#define KP_L  320   // K=300,  PS=5, NK16=19
#define KP_HV 448   // K=444,  PS=7, NK16=28 (exact)
#define KP_R1 512   // K=500,  PS=8, NK16=32 (exact)
#define KP_R2 576   // K=550,  PS=9, NK16=35
#define KP_R3 384   // K=378,  PS=6, NK16=24 (exact)

#define MV_OFF 144  // 16-aligned start of mv block inside A_hv
#define WA_GAP 11   // gap length (144-133)

#define NT_H  5
#define NT_R1 9
#define NT_R2 6
#define NT_R3 1

// ---------------- scratch ----------------
__device__ float g_h0[(size_t)EEDGE*HH];
__device__ float g_r1[(size_t)BB*RR1];
__device__ float g_r2[(size_t)BB*RR2];

__device__ __nv_bfloat16 g_Ae [(size_t)EEDGE*2*KP_L];
__device__ __nv_bfloat16 g_Ae2[(size_t)EEDGE*2*KP_L];
__device__ __nv_bfloat16 g_Ahv[(size_t)NNODE*2*KP_HV];
__device__ __nv_bfloat16 g_Ar1[(size_t)BB*2*KP_R1];
__device__ __nv_bfloat16 g_Ar2[(size_t)BB*2*KP_R2];
__device__ __nv_bfloat16 g_Ar3[(size_t)BB*2*KP_R3];

// W panels: [ntile][3P][64 rows x 128B] swizzled bf16
__device__ __nv_bfloat16 g_Wi [(size_t)NT_H *9 *64*64];
__device__ __nv_bfloat16 g_Wm [(size_t)NT_H *15*64*64];
__device__ __nv_bfloat16 g_Wa [(size_t)NT_H *21*64*64];
__device__ __nv_bfloat16 g_Wr1[(size_t)NT_R1*24*64*64];
__device__ __nv_bfloat16 g_Wr2[(size_t)NT_R2*27*64*64];
__device__ __nv_bfloat16 g_Wr3[(size_t)NT_R3*18*64*64];

// ---------------- helpers ----------------
__device__ __forceinline__ uint32_t smem_u32(const void* p){
    uint32_t a;
    asm("{ .reg .u64 t; cvta.to.shared.u64 t, %1; cvt.u32.u64 %0, t; }" : "=r"(a) : "l"(p));
    return a;
}
__device__ __forceinline__ void cp16(uint32_t dst, const void* src){
    asm volatile("cp.async.cg.shared.global [%0], [%1], 16;" :: "r"(dst), "l"(src));
}
__device__ __forceinline__ void cp_commit(){
    asm volatile("cp.async.commit_group;" ::: "memory");
}
__device__ __forceinline__ void ldm4(uint32_t& r0, uint32_t& r1, uint32_t& r2, uint32_t& r3, uint32_t addr){
    asm volatile("ldmatrix.sync.aligned.m8n8.x4.shared.b16 {%0,%1,%2,%3}, [%4];"
                 : "=r"(r0), "=r"(r1), "=r"(r2), "=r"(r3) : "r"(addr));
}
__device__ __forceinline__ void mma16816(float* c, const uint32_t* a, uint32_t b0, uint32_t b1){
    asm volatile("mma.sync.aligned.m16n8k16.row.col.f32.bf16.bf16.f32 "
                 "{%0,%1,%2,%3}, {%4,%5,%6,%7}, {%8,%9}, {%0,%1,%2,%3};"
                 : "+f"(c[0]), "+f"(c[1]), "+f"(c[2]), "+f"(c[3])
                 : "r"(a[0]), "r"(a[1]), "r"(a[2]), "r"(a[3]), "r"(b0), "r"(b1));
}
__device__ __forceinline__ void write_split(__nv_bfloat16* row, int Kpad, int k, float x){
    __nv_bfloat16 h = __float2bfloat16(x);
    row[k] = h;
    row[Kpad + k] = __float2bfloat16(x - __bfloat162float(h));
}
__device__ __forceinline__ void split_pair(float m0, float m1, __nv_bfloat16* base, int Kpad){
    __nv_bfloat16 a0 = __float2bfloat16(m0), a1 = __float2bfloat16(m1);
    __nv_bfloat162 hv2; hv2.x = a0; hv2.y = a1;
    __nv_bfloat162 lv2;
    lv2.x = __float2bfloat16(m0 - __bfloat162float(a0));
    lv2.y = __float2bfloat16(m1 - __bfloat162float(a1));
    *reinterpret_cast<__nv_bfloat162*>(base)        = hv2;
    *reinterpret_cast<__nv_bfloat162*>(base + Kpad) = lv2;
}
__device__ __forceinline__ uint32_t sw128(uint32_t off){ return off ^ ((off >> 3) & 0x70); }

// ---------------- weight prepack ----------------
__global__ void prepack_w(const float* __restrict__ W, __nv_bfloat16* __restrict__ out,
                          int K, int N, int P, int ntiles, int gap_start, int gap_len)
{
    int idx = blockIdx.x * 256 + threadIdx.x;
    const int per_panel = 64 * 64;
    int total = ntiles * 3 * P * per_panel;
    if (idx >= total) return;
    int t   = idx / (3 * P * per_panel);
    int rem = idx - t * (3 * P * per_panel);
    int g   = rem / per_panel;
    int rp  = rem - g * per_panel;
    int r   = rp >> 6;
    int kk  = rp & 63;
    int pass = g / P;
    int k    = (g - pass * P) * 64 + kk;
    int n    = t * 64 + r;
    int keff = (k < gap_start) ? k : k - gap_len;
    bool inGap = (k >= gap_start) && (k < gap_start + gap_len);
    float w = (!inGap && keff < K && n < N) ? W[(size_t)keff * N + n] : 0.f;
    __nv_bfloat16 v;
    if (pass == 1) { __nv_bfloat16 h = __float2bfloat16(w); v = __float2bfloat16(w - __bfloat162float(h)); }
    else           { v = __float2bfloat16(w); }
    uint32_t off = sw128((uint32_t)r * 128 + kk * 2);
    char* base = (char*)out + ((size_t)(t * 3 * P + g)) * 8192;
    *reinterpret_cast<__nv_bfloat16*>(base + off) = v;
}

// ---------------- warp-MMA GEMM, templated on storage panels / valid k16 ----------------
// mode 0: plain; mode 1: h->out + message->A2; mode 2: message->A2;
// mode 3: src-segment-sum -> A2 col MV_OFF; mode 4: per-graph mean -> A2.
#define NSTAGE 4
#define A_STAGE_BYTES 16384
#define W_STAGE_BYTES 8192
#define AOFF 1024
#define WOFF (1024 + NSTAGE * A_STAGE_BYTES)
#define GEMM_SMEM (WOFF + NSTAGE * W_STAGE_BYTES)
#define HSS 66

template<int PS, int NK16>
__global__ void __launch_bounds__(256, 2)
gemm_mma(const __nv_bfloat16* __restrict__ A, int astride,
         const char* __restrict__ Wp,
         const float* __restrict__ bias, const float* __restrict__ resid,
         float* __restrict__ out, int N, int relu,
         int mode, __nv_bfloat16* __restrict__ A2, int a2_kpad,
         const int* __restrict__ src_idx, const int* __restrict__ dst_idx)
{
    constexpr int Pv    = (NK16 + 3) / 4;          // valid panels per pass
    constexpr int PT    = 3 * Pv;
    constexpr int KTAIL = NK16 - 4 * (Pv - 1);     // k16 steps in last panel
    extern __shared__ char smem[];
    const int tid  = threadIdx.x;
    const int wid  = tid >> 5;
    const int lane = tid & 31;
    const uint32_t sbase = smem_u32(smem);
    const int Kpad = astride >> 1;                 // = PS*64
    const size_t row0 = (size_t)blockIdx.y * 128;
    const int colbase = blockIdx.x * 64;

    auto issue_loads = [&](int j){
        int s = j & (NSTAGE - 1);
        int pass = j / Pv;                         // Pv compile-time
        int p = j - pass * Pv;
        uint32_t abase = sbase + AOFF + s * A_STAGE_BYTES;
        int srcoff = ((pass == 2) ? Kpad : 0) + p * 64;
        #pragma unroll
        for (int i = 0; i < 4; i++) {
            int idx = tid + 256 * i;
            int r = idx >> 3, c = idx & 7;
            const char* src = (const char*)(A + (row0 + r) * (size_t)astride + srcoff) + c * 16;
            cp16(abase + sw128((uint32_t)r * 128 + c * 16), src);
        }
        const char* wsrc = Wp + ((size_t)(blockIdx.x * 3 * PS + pass * PS + p)) * 8192;
        uint32_t wbase = sbase + WOFF + s * W_STAGE_BYTES;
        #pragma unroll
        for (int jj = 0; jj < 2; jj++) {
            int widx = tid + 256 * jj;
            cp16(wbase + widx * 16, wsrc + (size_t)widx * 16);
        }
        cp_commit();
    };

    issue_loads(0); issue_loads(1); issue_loads(2);

    const int mw = wid & 3;
    const int nw = wid >> 2;
    float acc[2][4][4];
    #pragma unroll
    for (int i = 0; i < 2; i++)
        #pragma unroll
        for (int j = 0; j < 4; j++)
            #pragma unroll
            for (int q = 0; q < 4; q++) acc[i][j][q] = 0.f;

    const int q8 = lane >> 3;
    const int r8 = lane & 7;

    for (int g = 0; g < PT; g++) {
        int s = g & (NSTAGE - 1);
        int rem = PT - 1 - g;
        if (rem >= 2)      asm volatile("cp.async.wait_group 2;" ::: "memory");
        else if (rem == 1) asm volatile("cp.async.wait_group 1;" ::: "memory");
        else               asm volatile("cp.async.wait_group 0;" ::: "memory");
        __syncthreads();

        if (g + 3 < PT) issue_loads(g + 3);

        uint32_t abase = sbase + AOFF + s * A_STAGE_BYTES;
        uint32_t wbase = sbase + WOFF + s * W_STAGE_BYTES;

        auto do_ks = [&](int ks){
            const int kbyte = ks * 32;
            uint32_t a[2][4];
            #pragma unroll
            for (int tm = 0; tm < 2; tm++) {
                int arow = mw * 32 + tm * 16 + (q8 & 1) * 8 + r8;
                uint32_t off = sw128((uint32_t)arow * 128 + kbyte + (q8 >> 1) * 16);
                ldm4(a[tm][0], a[tm][1], a[tm][2], a[tm][3], abase + off);
            }
            uint32_t b[2][4];
            #pragma unroll
            for (int tb = 0; tb < 2; tb++) {
                int nrow = nw * 32 + tb * 16 + (q8 >> 1) * 8 + r8;
                uint32_t off = sw128((uint32_t)nrow * 128 + kbyte + (q8 & 1) * 16);
                ldm4(b[tb][0], b[tb][1], b[tb][2], b[tb][3], wbase + off);
            }
            #pragma unroll
            for (int tm = 0; tm < 2; tm++)
                #pragma unroll
                for (int tn = 0; tn < 4; tn++)
                    mma16816(acc[tm][tn], a[tm], b[tn >> 1][(tn & 1) * 2],
                             b[tn >> 1][(tn & 1) * 2 + 1]);
        };

        if constexpr (KTAIL == 4) {
            #pragma unroll
            for (int ks = 0; ks < 4; ks++) do_ks(ks);
        } else {
            int p = g - (g / Pv) * Pv;             // compile-time Pv
            if (p != Pv - 1) {
                #pragma unroll
                for (int ks = 0; ks < 4; ks++) do_ks(ks);
            } else {
                #pragma unroll
                for (int ks = 0; ks < KTAIL; ks++) do_ks(ks);
            }
        }
    }

    // ---- epilogue: activated values in registers ----
    float vals[2][2][4][2];
    #pragma unroll
    for (int tm = 0; tm < 2; tm++) {
        #pragma unroll
        for (int half = 0; half < 2; half++) {
            size_t r = row0 + mw * 32 + tm * 16 + (lane >> 2) + half * 8;
            #pragma unroll
            for (int tn = 0; tn < 4; tn++) {
                int c = colbase + nw * 32 + tn * 8 + (lane & 3) * 2;
                float v0 = 0.f, v1 = 0.f;
                if (c < N) {
                    float2 bv = *reinterpret_cast<const float2*>(&bias[c]);
                    v0 = acc[tm][tn][half * 2]     + bv.x;
                    v1 = acc[tm][tn][half * 2 + 1] + bv.y;
                    if (resid) {
                        float2 rv = *reinterpret_cast<const float2*>(&resid[r * N + c]);
                        v0 += rv.x; v1 += rv.y;
                    }
                    if (relu) { v0 = fmaxf(v0, 0.f); v1 = fmaxf(v1, 0.f); }
                    if (mode <= 1 && out) {
                        float2 q; q.x = v0; q.y = v1;
                        *reinterpret_cast<float2*>(&out[r * N + c]) = q;
                    }
                }
                vals[tm][half][tn][0] = v0;
                vals[tm][half][tn][1] = v1;
            }
        }
    }
    if (mode == 0) return;

    // ---- fused graph epilogue ----
    int*   s_src = (int*)smem;
    int*   s_dst = s_src + 128;
    float* hs    = (float*)(smem + 1024);
    float* accm  = hs + 128 * HSS;

    if (mode <= 3 && tid < 128) {
        s_src[tid] = src_idx[row0 + tid] - (int)(row0 >> 1);
        if (mode != 3) s_dst[tid] = dst_idx[row0 + tid] - (int)(row0 >> 1);
    }
    __syncthreads();

    #pragma unroll
    for (int tm = 0; tm < 2; tm++)
        #pragma unroll
        for (int half = 0; half < 2; half++) {
            int r_local = mw * 32 + tm * 16 + (lane >> 2) + half * 8;
            #pragma unroll
            for (int tn = 0; tn < 4; tn++) {
                int c_local = nw * 32 + tn * 8 + (lane & 3) * 2;
                float2 q; q.x = vals[tm][half][tn][0]; q.y = vals[tm][half][tn][1];
                *reinterpret_cast<float2*>(&hs[r_local * HSS + c_local]) = q;
            }
        }

    if (mode == 4) {
        __syncthreads();
        int gb = tid >> 6, c = tid & 63;
        int gc = colbase + c;
        if (gc < HH) {
            float s = 0.f;
            #pragma unroll 8
            for (int i = 0; i < 32; i++) s += hs[(gb * 32 + i) * HSS + c];
            write_split(A2 + ((row0 >> 5) + gb) * (size_t)(2 * a2_kpad), a2_kpad,
                        gc, s * (1.0f / NPER));
        }
        return;
    }

    for (int i = tid; i < 64 * HSS; i += 256) accm[i] = 0.f;
    __syncthreads();

    const int* agg = (mode == 3) ? s_src : s_dst;
    #pragma unroll 4
    for (int i = tid; i < 128 * 64; i += 256) {
        int e2 = i >> 6, c2 = i & 63;
        atomicAdd(&accm[agg[e2] * HSS + c2], hs[e2 * HSS + c2]);
    }
    __syncthreads();

    if (mode == 3) {
        for (int i = tid; i < 64 * 32; i += 256) {
            int n = i >> 5, cp = (i & 31) << 1;
            int gc = colbase + cp;
            if (gc < HH) {
                size_t base = ((row0 >> 1) + n) * (size_t)(2 * a2_kpad) + MV_OFF + gc;
                split_pair(accm[n * HSS + cp], accm[n * HSS + cp + 1], A2 + base, a2_kpad);
            }
        }
    } else {
        #pragma unroll 4
        for (int i = tid; i < 128 * 32; i += 256) {
            int e2 = i >> 5, cp = (i & 31) << 1;
            int sr = s_src[e2] * HSS;
            int rv = (e2 ^ 1) * HSS;
            size_t base = (row0 + e2) * (size_t)(2 * a2_kpad) + colbase + cp;
            split_pair(accm[sr + cp]     - hs[rv + cp],
                       accm[sr + cp + 1] - hs[rv + cp + 1], A2 + base, a2_kpad);
        }
    }
}

// ---------------- A' builders ----------------
// h0 GEMM reads only k16 0..9 -> write 160 cols
#define KW_H0 160
__global__ void conv_h0(const float* __restrict__ v, const float* __restrict__ e,
                        const int* __restrict__ src, __nv_bfloat16* __restrict__ A)
{
    size_t idx = (size_t)blockIdx.x * 256 + threadIdx.x;
    if (idx >= (size_t)EEDGE * KW_H0) return;
    int r = (int)(idx / KW_H0), k = (int)(idx % KW_H0);
    float x = 0.f;
    if (k < NF)            x = v[(size_t)src[r] * (NF + 1) + k];
    else if (k < NF + EFE) x = e[(size_t)r * (EFE + 1) + (k - NF)];
    write_split(A + (size_t)r * 2 * KP_H0, KP_H0, k, x);
}

#define VV_COLS (MV_OFF + (KP_HV - MV_OFF - HH))   // 148
__global__ void conv_vv(const float* __restrict__ v, __nv_bfloat16* __restrict__ A)
{
    size_t idx = (size_t)blockIdx.x * 256 + threadIdx.x;
    if (idx >= (size_t)NNODE * VV_COLS) return;
    int r = (int)(idx / VV_COLS), kc = (int)(idx % VV_COLS);
    int k = (kc < MV_OFF) ? kc : (MV_OFF + HH + (kc - MV_OFF));
    float x = (k < NF) ? v[(size_t)r * (NF + 1) + k] : 0.f;
    write_split(A + (size_t)r * 2 * KP_HV, KP_HV, k, x);
}

__global__ void glob_conv(const float* __restrict__ gl, __nv_bfloat16* __restrict__ A)
{
    size_t idx = (size_t)blockIdx.x * 256 + threadIdx.x;
    const int W = KP_R1 - HH;
    if (idx >= (size_t)BB * W) return;
    int b = (int)(idx / W), k = HH + (int)(idx % W);
    float x = (k < HH + GG) ? gl[(size_t)b * GG + (k - HH)] : 0.f;
    write_split(A + (size_t)b * 2 * KP_R1, KP_R1, k, x);
}

__global__ void conv_plain(const float* __restrict__ X, int Nin, int Kpad, int M,
                           __nv_bfloat16* __restrict__ A)
{
    size_t idx = (size_t)blockIdx.x * 256 + threadIdx.x;
    if (idx >= (size_t)M * Kpad) return;
    int r = (int)(idx / Kpad), k = (int)(idx % Kpad);
    float x = (k < Nin) ? X[(size_t)r * Nin + k] : 0.f;
    write_split(A + (size_t)r * 2 * Kpad, Kpad, k, x);
}

// ---------------- launch ----------------
extern "C" void kernel_launch(void* const* d_in, const int* in_sizes, int n_in,
                              void* d_out, int out_size)
{
    (void)in_sizes; (void)n_in; (void)out_size;
    const float* v   = (const float*)d_in[0];
    const float* e   = (const float*)d_in[1];
    const float* gl  = (const float*)d_in[2];
    const float* Wi  = (const float*)d_in[3];
    const float* bi  = (const float*)d_in[4];
    const float* Wm  = (const float*)d_in[5];
    const float* bm  = (const float*)d_in[6];
    const float* Wa  = (const float*)d_in[7];
    const float* ba  = (const float*)d_in[8];
    const float* Wr1 = (const float*)d_in[9];
    const float* br1 = (const float*)d_in[10];
    const float* Wr2 = (const float*)d_in[11];
    const float* br2 = (const float*)d_in[12];
    const float* Wr3 = (const float*)d_in[13];
    const float* br3 = (const float*)d_in[14];
    const int*   src = (const int*)d_in[15];
    const int*   dst = (const int*)d_in[16];
    float* out = (float*)d_out;

    float *h0, *r1, *r2;
    __nv_bfloat16 *Ae, *Ae2, *Ahv, *Ar1, *Ar2, *Ar3, *Wip, *Wmp, *Wap, *Wr1p, *Wr2p, *Wr3p;
    cudaGetSymbolAddress((void**)&h0, g_h0);
    cudaGetSymbolAddress((void**)&r1, g_r1);
    cudaGetSymbolAddress((void**)&r2, g_r2);
    cudaGetSymbolAddress((void**)&Ae,  g_Ae);
    cudaGetSymbolAddress((void**)&Ae2, g_Ae2);
    cudaGetSymbolAddress((void**)&Ahv, g_Ahv);
    cudaGetSymbolAddress((void**)&Ar1, g_Ar1);
    cudaGetSymbolAddress((void**)&Ar2, g_Ar2);
    cudaGetSymbolAddress((void**)&Ar3, g_Ar3);
    cudaGetSymbolAddress((void**)&Wip, g_Wi);
    cudaGetSymbolAddress((void**)&Wmp, g_Wm);
    cudaGetSymbolAddress((void**)&Wap, g_Wa);
    cudaGetSymbolAddress((void**)&Wr1p, g_Wr1);
    cudaGetSymbolAddress((void**)&Wr2p, g_Wr2);
    cudaGetSymbolAddress((void**)&Wr3p, g_Wr3);

    cudaFuncSetAttribute(gemm_mma<3,10>, cudaFuncAttributeMaxDynamicSharedMemorySize, GEMM_SMEM);
    cudaFuncSetAttribute(gemm_mma<5,19>, cudaFuncAttributeMaxDynamicSharedMemorySize, GEMM_SMEM);
    cudaFuncSetAttribute(gemm_mma<7,28>, cudaFuncAttributeMaxDynamicSharedMemorySize, GEMM_SMEM);
    cudaFuncSetAttribute(gemm_mma<8,32>, cudaFuncAttributeMaxDynamicSharedMemorySize, GEMM_SMEM);
    cudaFuncSetAttribute(gemm_mma<9,35>, cudaFuncAttributeMaxDynamicSharedMemorySize, GEMM_SMEM);
    cudaFuncSetAttribute(gemm_mma<6,24>, cudaFuncAttributeMaxDynamicSharedMemorySize, GEMM_SMEM);

    auto pk = [&](const float* W, __nv_bfloat16* o, int K, int N, int P, int nt,
                  int gs, int glen){
        int total = nt * 3 * P * 64 * 64;
        prepack_w<<<(total + 255) / 256, 256>>>(W, o, K, N, P, nt, gs, glen);
    };
    pk(Wi,  Wip,  NF + EFE, HH,  3, NT_H,  0, 0);
    pk(Wm,  Wmp,  HH,       HH,  5, NT_H,  0, 0);
    pk(Wa,  Wap,  NF + HH,  HH,  7, NT_H,  NF, WA_GAP);
    pk(Wr1, Wr1p, HH + GG,  RR1, 8, NT_R1, 0, 0);
    pk(Wr2, Wr2p, RR1,      RR2, 9, NT_R2, 0, 0);
    pk(Wr3, Wr3p, RR2,      TT,  6, NT_R3, 0, 0);

    conv_vv<<<(int)(((size_t)NNODE * VV_COLS + 255) / 256), 256>>>(v, Ahv);
    glob_conv<<<(int)(((size_t)BB * (KP_R1 - HH) + 255) / 256), 256>>>(gl, Ar1);

    // ---- 1) h0 GEMM (mode 1: h0 + me1 -> Ae2) ----
    conv_h0<<<(int)(((size_t)EEDGE * KW_H0 + 255) / 256), 256>>>(v, e, src, Ae);
    gemm_mma<3,10><<<dim3(NT_H, EEDGE / 128), 256, GEMM_SMEM>>>(
        Ae, 2 * KP_H0, (const char*)Wip, bi, nullptr, h0, HH, 1,
        1, Ae2, KP_L, src, dst);

    // ---- 2) message-passing layers ----
    gemm_mma<5,19><<<dim3(NT_H, EEDGE / 128), 256, GEMM_SMEM>>>(
        Ae2, 2 * KP_L, (const char*)Wmp, bm, h0, nullptr, HH, 1,
        2, Ae, KP_L, src, dst);
    gemm_mma<5,19><<<dim3(NT_H, EEDGE / 128), 256, GEMM_SMEM>>>(
        Ae, 2 * KP_L, (const char*)Wmp, bm, h0, nullptr, HH, 1,
        2, Ae2, KP_L, src, dst);
    gemm_mma<5,19><<<dim3(NT_H, EEDGE / 128), 256, GEMM_SMEM>>>(
        Ae2, 2 * KP_L, (const char*)Wmp, bm, h0, nullptr, HH, 1,
        3, Ahv, KP_HV, src, dst);

    // ---- 3) node MLP (mode 4: mean -> Ar1) ----
    gemm_mma<7,28><<<dim3(NT_H, NNODE / 128), 256, GEMM_SMEM>>>(
        Ahv, 2 * KP_HV, (const char*)Wap, ba, nullptr, nullptr, HH, 1,
        4, Ar1, KP_R1, nullptr, nullptr);

    // ---- 4) readout MLP ----
    gemm_mma<8,32><<<dim3(NT_R1, BB / 128), 256, GEMM_SMEM>>>(
        Ar1, 2 * KP_R1, (const char*)Wr1p, br1, nullptr, r1, RR1, 1,
        0, nullptr, 0, nullptr, nullptr);
    conv_plain<<<(int)(((size_t)BB * KP_R2 + 255) / 256), 256>>>(r1, RR1, KP_R2, BB, Ar2);
    gemm_mma<9,35><<<dim3(NT_R2, BB / 128), 256, GEMM_SMEM>>>(
        Ar2, 2 * KP_R2, (const char*)Wr2p, br2, nullptr, r2, RR2, 1,
        0, nullptr, 0, nullptr, nullptr);
    conv_plain<<<(int)(((size_t)BB * KP_R3 + 255) / 256), 256>>>(r2, RR2, KP_R3, BB, Ar3);
    gemm_mma<6,24><<<dim3(NT_R3, BB / 128), 256, GEMM_SMEM>>>(
        Ar3, 2 * KP_R3, (const char*)Wr3p, br3, nullptr, out, TT, 0,
        0, nullptr, 0, nullptr, nullptr);
}